// round 1
// baseline (speedup 1.0000x reference)
#include <cuda_runtime.h>
#include <math.h>

// ---------------- problem constants ----------------
#define SEGN   32
#define LSEG   512
#define RQ     64        // queries per segment
#define POOLN  8
#define NH     32
#define HDIM   128
#define DIM    4096
#define NQ     (SEGN*RQ)     // 2048
#define NTOK   (SEGN*LSEG)   // 16384
#define KVW    (2*NH*HDIM)   // 8192
#define EPS    1e-5f

// ---------------- scratch (device globals; allocation-free) ----------------
__device__ __align__(128) float g_queries[(size_t)NQ*DIM];   // pre-norm queries (residual)
__device__ __align__(128) float g_qn[(size_t)NQ*DIM];        // rmsnormed queries
__device__ __align__(128) float g_q[(size_t)NQ*DIM];         // q projection
__device__ __align__(128) float g_kv[(size_t)NTOK*KVW];      // kv projection (512 MB)
__device__ __align__(128) float g_o[(size_t)NQ*DIM];         // attention output
__device__ __align__(128) float g_tmp[(size_t)NQ*DIM];       // o @ wo

// ---------------- kernel 1: pooling + attention rmsnorm ----------------
__global__ void pool_rmsnorm_kernel(const float* __restrict__ x,
                                    const float* __restrict__ w) {
    int row = blockIdx.x;          // 0..NQ-1
    int tid = threadIdx.x;         // 256 threads
    const float* base = x + (size_t)row * POOLN * DIM;
    float local = 0.f;
    for (int d = tid; d < DIM; d += 256) {
        float s = 0.f;
        #pragma unroll
        for (int p = 0; p < POOLN; p++) s += base[(size_t)p*DIM + d];
        s *= (1.0f / POOLN);
        g_queries[(size_t)row*DIM + d] = s;
        local += s * s;
    }
    __shared__ float red[256];
    red[tid] = local; __syncthreads();
    for (int st = 128; st > 0; st >>= 1) {
        if (tid < st) red[tid] += red[tid + st];
        __syncthreads();
    }
    float rstd = rsqrtf(red[0] / DIM + EPS);
    for (int d = tid; d < DIM; d += 256)
        g_qn[(size_t)row*DIM + d] = g_queries[(size_t)row*DIM + d] * rstd * w[d];
}

// ---------------- kernel 2: fp32 tiled SGEMM (C = A @ B), 128x128x8 ----------------
// A: [M,K] row-major, B: [K,N] row-major, C: [M,N]. All dims multiples of 128/8.
__global__ __launch_bounds__(256, 2)
void sgemm_kernel(int M, int N, int K,
                  const float* __restrict__ A,
                  const float* __restrict__ B,
                  float* __restrict__ C) {
    const int BM = 128, BN = 128, BK = 8, TM = 8, TN = 8;
    __shared__ __align__(16) float Ast[BK][BM];   // A tile transposed
    __shared__ __align__(16) float Bs[BK][BN];
    int bx = blockIdx.x, by = blockIdx.y;
    int tid = threadIdx.x;
    int tx = tid % (BN / TN);   // 0..15
    int ty = tid / (BN / TN);   // 0..15
    const float* Ab = A + (size_t)by * BM * K;
    const float* Bb = B + (size_t)bx * BN;
    float acc[TM][TN];
    #pragma unroll
    for (int i = 0; i < TM; i++)
        #pragma unroll
        for (int j = 0; j < TN; j++) acc[i][j] = 0.f;

    int arow = tid >> 1;           // 0..127
    int acol = (tid & 1) * 4;      // 0 or 4
    int brow = tid >> 5;           // 0..7
    int bcol = (tid & 31) * 4;     // 0..124

    for (int k0 = 0; k0 < K; k0 += BK) {
        float4 av = *reinterpret_cast<const float4*>(Ab + (size_t)arow * K + k0 + acol);
        Ast[acol + 0][arow] = av.x;
        Ast[acol + 1][arow] = av.y;
        Ast[acol + 2][arow] = av.z;
        Ast[acol + 3][arow] = av.w;
        *reinterpret_cast<float4*>(&Bs[brow][bcol]) =
            *reinterpret_cast<const float4*>(Bb + (size_t)(k0 + brow) * N + bcol);
        __syncthreads();
        #pragma unroll
        for (int k = 0; k < BK; k++) {
            float ra[TM], rb[TN];
            #pragma unroll
            for (int i = 0; i < TM; i++) ra[i] = Ast[k][ty * TM + i];
            #pragma unroll
            for (int j = 0; j < TN; j++) rb[j] = Bs[k][tx * TN + j];
            #pragma unroll
            for (int i = 0; i < TM; i++)
                #pragma unroll
                for (int j = 0; j < TN; j++)
                    acc[i][j] += ra[i] * rb[j];
        }
        __syncthreads();
    }
    #pragma unroll
    for (int i = 0; i < TM; i++) {
        float* crow = C + (size_t)(by * BM + ty * TM + i) * N + bx * BN + tx * TN;
        #pragma unroll
        for (int j = 0; j < TN; j += 4) {
            float4 v = make_float4(acc[i][j], acc[i][j+1], acc[i][j+2], acc[i][j+3]);
            *reinterpret_cast<float4*>(crow + j) = v;
        }
    }
}

// ---------------- kernel 3: per-(seg, head, 16-query tile) attention ----------------
#define RT  16   // query rows per block
#define KC  64   // key chunk rows
#define ATT_SMEM ((RT*HDIM + KC*(HDIM+1) + RT*LSEG + RT) * sizeof(float))

__global__ __launch_bounds__(128)
void attention_kernel() {
    extern __shared__ float sm[];
    float* Qs   = sm;                          // RT * HDIM
    float* Ks   = Qs + RT * HDIM;              // KC * (HDIM+1), padded rows
    float* Ss   = Ks + KC * (HDIM + 1);        // RT * LSEG scores/probs
    float* rsum = Ss + RT * LSEG;              // RT

    int rt = blockIdx.x;      // 0..(RQ/RT)-1 = 0..3
    int h  = blockIdx.y;      // 0..NH-1
    int s  = blockIdx.z;      // 0..SEGN-1
    int tid = threadIdx.x;    // 128 threads

    int q_row0 = s * RQ + rt * RT;

    // load Q tile [RT][HDIM]
    for (int i = tid; i < RT * HDIM; i += 128) {
        int r = i / HDIM, d = i % HDIM;
        Qs[r * HDIM + d] = g_q[(size_t)(q_row0 + r) * DIM + h * HDIM + d];
    }

    const float scale = rsqrtf((float)HDIM);
    int g = tid / KC;     // 0..1 : which 8-row query group
    int l = tid % KC;     // key row within chunk
    __syncthreads();

    // Phase 1: scores S[RT][LSEG] = scale * Q Kt
    for (int lc = 0; lc < LSEG; lc += KC) {
        // cooperative load of K chunk [KC][HDIM] (coalesced float4, padded smem)
        for (int i = tid; i < KC * (HDIM / 4); i += 128) {
            int kr = i / (HDIM / 4);
            int c4 = i % (HDIM / 4);
            float4 v = *reinterpret_cast<const float4*>(
                &g_kv[(size_t)(s * LSEG + lc + kr) * KVW + h * HDIM + c4 * 4]);
            float* dst = &Ks[kr * (HDIM + 1) + c4 * 4];
            dst[0] = v.x; dst[1] = v.y; dst[2] = v.z; dst[3] = v.w;
        }
        __syncthreads();
        float acc[8];
        #pragma unroll
        for (int r8 = 0; r8 < 8; r8++) acc[r8] = 0.f;
        #pragma unroll 4
        for (int d = 0; d < HDIM; d++) {
            float kv = Ks[l * (HDIM + 1) + d];
            #pragma unroll
            for (int r8 = 0; r8 < 8; r8++)
                acc[r8] += Qs[(g * 8 + r8) * HDIM + d] * kv;
        }
        #pragma unroll
        for (int r8 = 0; r8 < 8; r8++)
            Ss[(g * 8 + r8) * LSEG + lc + l] = acc[r8] * scale;
        __syncthreads();
    }

    // Phase 2: softmax per row (one warp -> 4 rows)
    int warp = tid / 32, lane = tid % 32;
    for (int r = warp; r < RT; r += 4) {
        float m = -1e30f;
        for (int i = lane; i < LSEG; i += 32) m = fmaxf(m, Ss[r * LSEG + i]);
        #pragma unroll
        for (int o = 16; o; o >>= 1) m = fmaxf(m, __shfl_xor_sync(0xffffffffu, m, o));
        float sum = 0.f;
        for (int i = lane; i < LSEG; i += 32) {
            float e = __expf(Ss[r * LSEG + i] - m);
            Ss[r * LSEG + i] = e;
            sum += e;
        }
        #pragma unroll
        for (int o = 16; o; o >>= 1) sum += __shfl_xor_sync(0xffffffffu, sum, o);
        if (lane == 0) rsum[r] = 1.0f / sum;
    }
    __syncthreads();

    // Phase 3: O[RT][HDIM] = P V ; thread owns output column c = tid
    int c = tid;
    float oacc[RT];
    #pragma unroll
    for (int r = 0; r < RT; r++) oacc[r] = 0.f;
    const float* vbase = &g_kv[(size_t)(s * LSEG) * KVW + NH * HDIM + h * HDIM + c];
    #pragma unroll 4
    for (int lk = 0; lk < LSEG; lk++) {
        float vv = vbase[(size_t)lk * KVW];
        #pragma unroll
        for (int r = 0; r < RT; r++) oacc[r] += Ss[r * LSEG + lk] * vv;
    }
    #pragma unroll
    for (int r = 0; r < RT; r++)
        g_o[(size_t)(q_row0 + r) * DIM + h * HDIM + c] = oacc[r] * rsum[r];
}

// ---------------- kernel 4: residual + output rmsnorm ----------------
__global__ void final_kernel(const float* __restrict__ w, float* __restrict__ out) {
    int row = blockIdx.x;
    int tid = threadIdx.x;  // 256
    float vals[DIM / 256];
    float local = 0.f;
    #pragma unroll
    for (int i = 0; i < DIM / 256; i++) {
        int d = tid + i * 256;
        float v = g_tmp[(size_t)row * DIM + d] + g_queries[(size_t)row * DIM + d];
        vals[i] = v;
        local += v * v;
    }
    __shared__ float red[256];
    red[tid] = local; __syncthreads();
    for (int st = 128; st > 0; st >>= 1) {
        if (tid < st) red[tid] += red[tid + st];
        __syncthreads();
    }
    float rstd = rsqrtf(red[0] / DIM + EPS);
    #pragma unroll
    for (int i = 0; i < DIM / 256; i++) {
        int d = tid + i * 256;
        out[(size_t)row * DIM + d] = vals[i] * rstd * w[d];
    }
}

// ---------------- launch ----------------
extern "C" void kernel_launch(void* const* d_in, const int* in_sizes, int n_in,
                              void* d_out, int out_size) {
    const float* x      = (const float*)d_in[0];
    const float* attn_w = (const float*)d_in[1];
    const float* wq     = (const float*)d_in[2];
    const float* wkv    = (const float*)d_in[3];
    const float* wo     = (const float*)d_in[4];
    const float* out_w  = (const float*)d_in[5];
    float* out = (float*)d_out;

    float *pqn, *pq, *pkv, *po, *ptmp;
    cudaGetSymbolAddress((void**)&pqn,  g_qn);
    cudaGetSymbolAddress((void**)&pq,   g_q);
    cudaGetSymbolAddress((void**)&pkv,  g_kv);
    cudaGetSymbolAddress((void**)&po,   g_o);
    cudaGetSymbolAddress((void**)&ptmp, g_tmp);

    cudaFuncSetAttribute(attention_kernel,
                         cudaFuncAttributeMaxDynamicSharedMemorySize, (int)ATT_SMEM);

    // 1. pooling + attention rmsnorm
    pool_rmsnorm_kernel<<<NQ, 256>>>(x, attn_w);

    // 2. q = qn @ wq  [2048, 4096, 4096]
    sgemm_kernel<<<dim3(DIM / 128, NQ / 128), 256>>>(NQ, DIM, DIM, pqn, wq, pq);

    // 3. kv = x @ wkv  [16384, 8192, 4096]  (dominant GEMM)
    sgemm_kernel<<<dim3(KVW / 128, NTOK / 128), 256>>>(NTOK, KVW, DIM, x, wkv, pkv);

    // 4. per-segment attention
    attention_kernel<<<dim3(RQ / RT, NH, SEGN), 128, ATT_SMEM>>>();

    // 5. tmp = o @ wo  [2048, 4096, 4096]
    sgemm_kernel<<<dim3(DIM / 128, NQ / 128), 256>>>(NQ, DIM, DIM, po, wo, ptmp);

    // 6. residual + output rmsnorm
    final_kernel<<<NQ, 256>>>(out_w, out);
}

// round 3
// speedup vs baseline: 4.9107x; 4.9107x over previous
#include <cuda_runtime.h>
#include <cuda_bf16.h>
#include <math.h>
#include <stdint.h>

// ---------------- problem constants ----------------
#define SEGN   32
#define LSEG   512
#define RQ     64
#define POOLN  8
#define NH     32
#define HDIM   128
#define DIM    4096
#define NQ     (SEGN*RQ)     // 2048
#define NTOK   (SEGN*LSEG)   // 16384
#define KVW    (2*NH*HDIM)   // 8192
#define EPS    1e-5f

// arch-specific feature gate (tcgen05/TMEM need the 'a' target)
#if defined(__CUDA_ARCH_FEAT_SM103_ALL) || defined(__CUDA_ARCH_FEAT_SM100_ALL)
#define TC_OK 1
#else
#define TC_OK 0
#endif

// ---------------- scratch ----------------
__device__ __align__(128) float g_queries[(size_t)NQ*DIM];
__device__ __align__(128) float g_q[(size_t)NQ*DIM];
__device__ __align__(128) float g_kv[(size_t)NTOK*KVW];
__device__ __align__(128) float g_tmp[(size_t)NQ*DIM];

__device__ __align__(128) __nv_bfloat16 g_a_hi[(size_t)NTOK*DIM];
__device__ __align__(128) __nv_bfloat16 g_a_lo[(size_t)NTOK*DIM];
__device__ __align__(128) __nv_bfloat16 g_bkv_hi[(size_t)KVW*DIM];
__device__ __align__(128) __nv_bfloat16 g_bkv_lo[(size_t)KVW*DIM];
__device__ __align__(128) __nv_bfloat16 g_bq_hi[(size_t)DIM*DIM];
__device__ __align__(128) __nv_bfloat16 g_bq_lo[(size_t)DIM*DIM];
__device__ __align__(128) __nv_bfloat16 g_bo_hi[(size_t)DIM*DIM];
__device__ __align__(128) __nv_bfloat16 g_bo_lo[(size_t)DIM*DIM];
__device__ __align__(128) __nv_bfloat16 g_qn_hi[(size_t)NQ*DIM];
__device__ __align__(128) __nv_bfloat16 g_qn_lo[(size_t)NQ*DIM];
__device__ __align__(128) __nv_bfloat16 g_o_hi[(size_t)NQ*DIM];
__device__ __align__(128) __nv_bfloat16 g_o_lo[(size_t)NQ*DIM];

// ---------------- generic helpers ----------------
__device__ __forceinline__ uint32_t s2u(const void* p) {
    return (uint32_t)__cvta_generic_to_shared(p);
}
__device__ __forceinline__ void mbar_init(uint32_t a, uint32_t cnt) {
    asm volatile("mbarrier.init.shared.b64 [%0], %1;" :: "r"(a), "r"(cnt) : "memory");
}
__device__ __forceinline__ void mbar_wait(uint32_t a, uint32_t phase) {
    uint32_t done;
    do {
        asm volatile("{\n\t.reg .pred p;\n\t"
                     "mbarrier.try_wait.parity.shared::cta.b64 p, [%1], %2, 0x989680;\n\t"
                     "selp.b32 %0, 1, 0, p;\n\t}"
                     : "=r"(done) : "r"(a), "r"(phase) : "memory");
    } while (!done);
}
__device__ __forceinline__ void cp_async16(uint32_t dst, const void* src) {
    asm volatile("cp.async.cg.shared.global [%0], [%1], 16;" :: "r"(dst), "l"(src) : "memory");
}
__device__ __forceinline__ void cp_async_arrive(uint32_t bar) {
    asm volatile("cp.async.mbarrier.arrive.noinc.shared::cta.b64 [%0];" :: "r"(bar) : "memory");
}
__device__ __forceinline__ uint32_t swz(uint32_t off) {
    return off ^ ((off >> 3) & 0x70u);
}

#if TC_OK
// ---------------- tcgen05 helpers (only on 'a' targets) ----------------
__device__ __forceinline__ void tc_alloc(uint32_t smem_dst, uint32_t ncols) {
    asm volatile("tcgen05.alloc.cta_group::1.sync.aligned.shared::cta.b32 [%0], %1;"
                 :: "r"(smem_dst), "r"(ncols) : "memory");
}
__device__ __forceinline__ void tc_dealloc(uint32_t tmem, uint32_t ncols) {
    asm volatile("tcgen05.relinquish_alloc_permit.cta_group::1.sync.aligned;");
    asm volatile("tcgen05.dealloc.cta_group::1.sync.aligned.b32 %0, %1;" :: "r"(tmem), "r"(ncols));
}
__device__ __forceinline__ void tc_commit(uint32_t bar) {
    asm volatile("tcgen05.commit.cta_group::1.mbarrier::arrive::one.shared::cluster.b64 [%0];"
                 :: "r"(bar) : "memory");
}
__device__ __forceinline__ void tc_mma_f16_ss(uint32_t d, uint64_t ad, uint64_t bd,
                                              uint32_t idesc, uint32_t accum) {
    asm volatile("{\n\t.reg .pred p;\n\t"
                 "setp.ne.u32 p, %4, 0;\n\t"
                 "tcgen05.mma.cta_group::1.kind::f16 [%0], %1, %2, %3, {%5, %5, %5, %5}, p;\n\t}"
                 :: "r"(d), "l"(ad), "l"(bd), "r"(idesc), "r"(accum), "r"(0u) : "memory");
}
__device__ __forceinline__ void tc_fence_after() {
    asm volatile("tcgen05.fence::after_thread_sync;" ::: "memory");
}
__device__ __forceinline__ void fence_proxy_async_s() {
    asm volatile("fence.proxy.async.shared::cta;" ::: "memory");
}
#define LDTM_X32(r, addr) \
    asm volatile("tcgen05.ld.sync.aligned.32x32b.x32.b32 " \
        "{%0, %1, %2, %3, %4, %5, %6, %7, %8, %9, %10, %11, %12, %13, %14, %15, " \
        "%16, %17, %18, %19, %20, %21, %22, %23, %24, %25, %26, %27, %28, %29, %30, %31}, [%32];" \
        : "=r"((r)[0]), "=r"((r)[1]), "=r"((r)[2]), "=r"((r)[3]), \
          "=r"((r)[4]), "=r"((r)[5]), "=r"((r)[6]), "=r"((r)[7]), \
          "=r"((r)[8]), "=r"((r)[9]), "=r"((r)[10]), "=r"((r)[11]), \
          "=r"((r)[12]), "=r"((r)[13]), "=r"((r)[14]), "=r"((r)[15]), \
          "=r"((r)[16]), "=r"((r)[17]), "=r"((r)[18]), "=r"((r)[19]), \
          "=r"((r)[20]), "=r"((r)[21]), "=r"((r)[22]), "=r"((r)[23]), \
          "=r"((r)[24]), "=r"((r)[25]), "=r"((r)[26]), "=r"((r)[27]), \
          "=r"((r)[28]), "=r"((r)[29]), "=r"((r)[30]), "=r"((r)[31]) \
        : "r"(addr))
__device__ __forceinline__ void tc_wait_ld() {
    asm volatile("tcgen05.wait::ld.sync.aligned;" ::: "memory");
}
static __device__ __forceinline__ uint64_t make_desc(uint32_t addr) {
    const uint64_t base = (uint64_t(2) << 61) | (uint64_t(1) << 46) |
                          (uint64_t(64) << 32) | (uint64_t(1) << 16);
    return base | ((uint64_t)(addr >> 4) & 0x3FFFull);
}
#else
// ---------------- mma.sync helper (portable PTX, runs on bare sm_103) ----------------
__device__ __forceinline__ void mma16816(float* c, const uint32_t* a, uint32_t b0, uint32_t b1) {
    asm volatile("mma.sync.aligned.m16n8k16.row.col.f32.bf16.bf16.f32 "
                 "{%0,%1,%2,%3}, {%4,%5,%6,%7}, {%8,%9}, {%0,%1,%2,%3};"
                 : "+f"(c[0]), "+f"(c[1]), "+f"(c[2]), "+f"(c[3])
                 : "r"(a[0]), "r"(a[1]), "r"(a[2]), "r"(a[3]), "r"(b0), "r"(b1));
}
#endif

// ---------------- elementwise split / transpose-split ----------------
__global__ void split_kernel(const float* __restrict__ in,
                             __nv_bfloat16* __restrict__ hi,
                             __nv_bfloat16* __restrict__ lo) {
    size_t i = (size_t)blockIdx.x * blockDim.x + threadIdx.x;
    float a = in[i];
    __nv_bfloat16 h = __float2bfloat16(a);
    hi[i] = h;
    lo[i] = __float2bfloat16(a - __bfloat162float(h));
}

// in: [Kdim, Ndim] row-major fp32  ->  hi/lo: [Ndim, Kdim] bf16 (transposed)
__global__ void tsplit_kernel(const float* __restrict__ in,
                              __nv_bfloat16* __restrict__ hi,
                              __nv_bfloat16* __restrict__ lo,
                              int Kdim, int Ndim) {
    __shared__ float t[32][33];
    int n0 = blockIdx.x * 32, k0 = blockIdx.y * 32;
    int tx = threadIdx.x, ty = threadIdx.y;
    for (int r = ty; r < 32; r += 8)
        t[r][tx] = in[(size_t)(k0 + r) * Ndim + n0 + tx];
    __syncthreads();
    for (int r = ty; r < 32; r += 8) {
        float a = t[tx][r];
        size_t o = (size_t)(n0 + r) * Kdim + k0 + tx;
        __nv_bfloat16 h = __float2bfloat16(a);
        hi[o] = h;
        lo[o] = __float2bfloat16(a - __bfloat162float(h));
    }
}

// ---------------- pooling + attention rmsnorm (emits bf16 hi/lo) ----------------
__global__ void pool_rmsnorm_kernel(const float* __restrict__ x,
                                    const float* __restrict__ w) {
    int row = blockIdx.x;
    int tid = threadIdx.x;
    const float* base = x + (size_t)row * POOLN * DIM;
    float local = 0.f;
    for (int d = tid; d < DIM; d += 256) {
        float s = 0.f;
        #pragma unroll
        for (int p = 0; p < POOLN; p++) s += base[(size_t)p*DIM + d];
        s *= (1.0f / POOLN);
        g_queries[(size_t)row*DIM + d] = s;
        local += s * s;
    }
    __shared__ float red[256];
    red[tid] = local; __syncthreads();
    for (int st = 128; st > 0; st >>= 1) {
        if (tid < st) red[tid] += red[tid + st];
        __syncthreads();
    }
    float rstd = rsqrtf(red[0] / DIM + EPS);
    for (int d = tid; d < DIM; d += 256) {
        float v = g_queries[(size_t)row*DIM + d] * rstd * w[d];
        __nv_bfloat16 h = __float2bfloat16(v);
        g_qn_hi[(size_t)row*DIM + d] = h;
        g_qn_lo[(size_t)row*DIM + d] = __float2bfloat16(v - __bfloat162float(h));
    }
}

// ---------------- bf16x3 GEMM: C[M,N] = A[M,K] @ B[N,K]^T, K = 4096 ----------------
#define BM 128
#define BN 256
#define GK 4096
#define KITERS (GK/64)
#define ABYTES 16384u
#define BBYTES 32768u
#define STAGE_BYTES (2u*ABYTES + 2u*BBYTES)  // 98304
#define CHUNKS 6144
#define GEMM_SMEM (2*STAGE_BYTES + 1024)

__global__ __launch_bounds__(256, 1)
void gemm3_kernel(int N, int nbm, int nbn,
                  const __nv_bfloat16* __restrict__ Ah,
                  const __nv_bfloat16* __restrict__ Al,
                  const __nv_bfloat16* __restrict__ Bh,
                  const __nv_bfloat16* __restrict__ Bl,
                  float* __restrict__ C) {
    extern __shared__ char smraw[];
    char* smp = (char*)((((uintptr_t)smraw) + 1023) & ~(uintptr_t)1023);
    int tid = threadIdx.x;

    // swizzled tile mapping (GROUP_M = 16)
    const int GM = 16;
    int bid = blockIdx.x;
    int group = bid / (GM * nbn);
    int first_m = group * GM;
    int gsz = min(nbm - first_m, GM);
    int pm = first_m + (bid % gsz);
    int pn = (bid % (GM * nbn)) / gsz;
    int m0 = pm * BM, n0 = pn * BN;

#if TC_OK
    // ======== tcgen05 pipeline (sm_103a path) ========
    uint32_t sb0 = s2u(smp);
    __shared__ __align__(8) unsigned long long full_b[2], empty_b[2], fin_b;
    __shared__ uint32_t tmem_ptr_sh;

    uint32_t full_a[2], empty_a[2], fin_a;
    full_a[0] = s2u(&full_b[0]); full_a[1] = s2u(&full_b[1]);
    empty_a[0] = s2u(&empty_b[0]); empty_a[1] = s2u(&empty_b[1]);
    fin_a = s2u(&fin_b);

    if (tid < 32) tc_alloc(s2u(&tmem_ptr_sh), 256);
    if (tid == 0) {
        mbar_init(full_a[0], 224); mbar_init(full_a[1], 224);
        mbar_init(empty_a[0], 1);  mbar_init(empty_a[1], 1);
        mbar_init(fin_a, 1);
    }
    __syncthreads();
    uint32_t tmem = tmem_ptr_sh;

    const uint32_t idesc = (1u<<4) | (1u<<7) | (1u<<10) | ((BN/8)<<17) | ((BM/16)<<24);

    if (tid >= 32) {
        // producers (224 threads)
        for (int it = 0; it < KITERS; it++) {
            int s = it & 1;
            uint32_t ph = ((it >> 1) & 1) ^ 1u;
            mbar_wait(empty_a[s], ph);
            int k0 = it * 64;
            uint32_t sb = sb0 + s * STAGE_BYTES;
            for (int i = tid - 32; i < CHUNKS; i += 224) {
                const __nv_bfloat16* src;
                uint32_t dst;
                if (i < 2048) {
                    int hi = (i < 1024);
                    int j = i & 1023;
                    int r = j >> 3, c = j & 7;
                    dst = sb + (hi ? 0u : ABYTES) + swz(r * 128 + c * 16);
                    src = (hi ? Ah : Al) + (size_t)(m0 + r) * GK + k0 + c * 8;
                } else {
                    int j = i - 2048;
                    int hi = (j < 2048);
                    j &= 2047;
                    int r = j >> 3, c = j & 7;
                    dst = sb + (hi ? 2u*ABYTES : 2u*ABYTES + BBYTES) + swz(r * 128 + c * 16);
                    src = (hi ? Bh : Bl) + (size_t)(n0 + r) * GK + k0 + c * 8;
                }
                cp_async16(dst, src);
            }
            cp_async_arrive(full_a[s]);
        }
    } else if (tid == 0) {
        // MMA issuer
        for (int it = 0; it < KITERS; it++) {
            int s = it & 1;
            uint32_t ph = (it >> 1) & 1;
            mbar_wait(full_a[s], ph);
            fence_proxy_async_s();
            uint32_t sb = sb0 + s * STAGE_BYTES;
            uint64_t adh = make_desc(sb);
            uint64_t adl = make_desc(sb + ABYTES);
            uint64_t bdh = make_desc(sb + 2u*ABYTES);
            uint64_t bdl = make_desc(sb + 2u*ABYTES + BBYTES);
            #pragma unroll
            for (int ks = 0; ks < 4; ks++) {
                uint32_t acc = (it > 0 || ks > 0) ? 1u : 0u;
                tc_mma_f16_ss(tmem, adh + ks*2, bdh + ks*2, idesc, acc);
                tc_mma_f16_ss(tmem, adh + ks*2, bdl + ks*2, idesc, 1u);
                tc_mma_f16_ss(tmem, adl + ks*2, bdh + ks*2, idesc, 1u);
            }
            tc_commit(empty_a[s]);
        }
        tc_commit(fin_a);
    }

    __syncthreads();
    mbar_wait(fin_a, 0);
    tc_fence_after();

    // epilogue: TMEM -> smem staging -> coalesced global
    float* stg = (float*)smp;
    int w = tid >> 5, lane = tid & 31;
    if (w < 4) {
        for (int ch = 0; ch < 8; ch++) {
            uint32_t r[32];
            LDTM_X32(r, tmem + ch * 32);
            tc_wait_ld();
            #pragma unroll
            for (int j = 0; j < 32; j++)
                stg[(size_t)(w * 32 + lane) * 260 + ch * 32 + j] = __uint_as_float(r[j]);
        }
    }
    __syncthreads();
    if (tid < 32) tc_dealloc(tmem, 256);
    for (int rr = tid >> 6; rr < BM; rr += 4) {
        int c4 = (tid & 63) * 4;
        float4 v = *(float4*)&stg[(size_t)rr * 260 + c4];
        *(float4*)&C[(size_t)(m0 + rr) * N + n0 + c4] = v;
    }
#else
    // ======== mma.sync bf16x3 fallback (bare sm_103 path) ========
    // smem tiles: 128 rows x 32 k, row stride 40 bf16 (80B) to dodge conflicts
    __nv_bfloat16* sAh = (__nv_bfloat16*)smp;
    __nv_bfloat16* sAl = sAh + 128 * 40;
    __nv_bfloat16* sBh = sAl + 128 * 40;
    __nv_bfloat16* sBl = sBh + 128 * 40;

    int lane = tid & 31, w = tid >> 5;
    int wm = w & 3, wn = w >> 2;         // 4x2 warp grid -> warp tile 32x64

    for (int half = 0; half < 2; half++) {
        int n0h = n0 + half * 128;
        float acc[2][8][4];
        #pragma unroll
        for (int mi = 0; mi < 2; mi++)
            #pragma unroll
            for (int ni = 0; ni < 8; ni++)
                #pragma unroll
                for (int j = 0; j < 4; j++) acc[mi][ni][j] = 0.f;

        for (int k0 = 0; k0 < GK; k0 += 32) {
            __syncthreads();
            for (int cid = tid; cid < 512; cid += 256) {
                int r = cid >> 2, c = cid & 3;
                *(uint4*)&sAh[r*40 + c*8] = *(const uint4*)&Ah[(size_t)(m0+r)*GK + k0 + c*8];
                *(uint4*)&sAl[r*40 + c*8] = *(const uint4*)&Al[(size_t)(m0+r)*GK + k0 + c*8];
                *(uint4*)&sBh[r*40 + c*8] = *(const uint4*)&Bh[(size_t)(n0h+r)*GK + k0 + c*8];
                *(uint4*)&sBl[r*40 + c*8] = *(const uint4*)&Bl[(size_t)(n0h+r)*GK + k0 + c*8];
            }
            __syncthreads();
            #pragma unroll
            for (int ks = 0; ks < 2; ks++) {
                int kc = (lane & 3) * 2 + ks * 16;
                uint32_t ah[2][4], al[2][4];
                #pragma unroll
                for (int mi = 0; mi < 2; mi++) {
                    int r = wm * 32 + mi * 16 + (lane >> 2);
                    ah[mi][0] = *(uint32_t*)&sAh[r*40 + kc];
                    ah[mi][1] = *(uint32_t*)&sAh[(r+8)*40 + kc];
                    ah[mi][2] = *(uint32_t*)&sAh[r*40 + kc + 8];
                    ah[mi][3] = *(uint32_t*)&sAh[(r+8)*40 + kc + 8];
                    al[mi][0] = *(uint32_t*)&sAl[r*40 + kc];
                    al[mi][1] = *(uint32_t*)&sAl[(r+8)*40 + kc];
                    al[mi][2] = *(uint32_t*)&sAl[r*40 + kc + 8];
                    al[mi][3] = *(uint32_t*)&sAl[(r+8)*40 + kc + 8];
                }
                #pragma unroll
                for (int ni = 0; ni < 8; ni++) {
                    int nr = wn * 64 + ni * 8 + (lane >> 2);
                    uint32_t bh0 = *(uint32_t*)&sBh[nr*40 + kc];
                    uint32_t bh1 = *(uint32_t*)&sBh[nr*40 + kc + 8];
                    uint32_t bl0 = *(uint32_t*)&sBl[nr*40 + kc];
                    uint32_t bl1 = *(uint32_t*)&sBl[nr*40 + kc + 8];
                    #pragma unroll
                    for (int mi = 0; mi < 2; mi++) {
                        mma16816(acc[mi][ni], ah[mi], bh0, bh1);
                        mma16816(acc[mi][ni], ah[mi], bl0, bl1);
                        mma16816(acc[mi][ni], al[mi], bh0, bh1);
                    }
                }
            }
        }
        #pragma unroll
        for (int mi = 0; mi < 2; mi++)
            #pragma unroll
            for (int ni = 0; ni < 8; ni++) {
                int r = m0 + wm * 32 + mi * 16 + (lane >> 2);
                int c = n0h + wn * 64 + ni * 8 + (lane & 3) * 2;
                *(float2*)&C[(size_t)r * N + c] = make_float2(acc[mi][ni][0], acc[mi][ni][1]);
                *(float2*)&C[(size_t)(r+8) * N + c] = make_float2(acc[mi][ni][2], acc[mi][ni][3]);
            }
    }
#endif
}

// ---------------- attention (emits bf16 hi/lo output) ----------------
#define RT  16
#define KC  64
#define ATT_SMEM ((RT*HDIM + KC*(HDIM+1) + RT*LSEG + RT) * sizeof(float))

__global__ __launch_bounds__(128)
void attention_kernel() {
    extern __shared__ float sm[];
    float* Qs   = sm;
    float* Ks   = Qs + RT * HDIM;
    float* Ss   = Ks + KC * (HDIM + 1);
    float* rsum = Ss + RT * LSEG;

    int rt = blockIdx.x;
    int h  = blockIdx.y;
    int s  = blockIdx.z;
    int tid = threadIdx.x;
    int q_row0 = s * RQ + rt * RT;

    for (int i = tid; i < RT * HDIM; i += 128) {
        int r = i / HDIM, d = i % HDIM;
        Qs[r * HDIM + d] = g_q[(size_t)(q_row0 + r) * DIM + h * HDIM + d];
    }
    const float scale = rsqrtf((float)HDIM);
    int g = tid / KC;
    int l = tid % KC;
    __syncthreads();

    for (int lc = 0; lc < LSEG; lc += KC) {
        for (int i = tid; i < KC * (HDIM / 4); i += 128) {
            int kr = i / (HDIM / 4);
            int c4 = i % (HDIM / 4);
            float4 v = *reinterpret_cast<const float4*>(
                &g_kv[(size_t)(s * LSEG + lc + kr) * KVW + h * HDIM + c4 * 4]);
            float* dst = &Ks[kr * (HDIM + 1) + c4 * 4];
            dst[0] = v.x; dst[1] = v.y; dst[2] = v.z; dst[3] = v.w;
        }
        __syncthreads();
        float acc[8];
        #pragma unroll
        for (int r8 = 0; r8 < 8; r8++) acc[r8] = 0.f;
        #pragma unroll 4
        for (int d = 0; d < HDIM; d++) {
            float kv = Ks[l * (HDIM + 1) + d];
            #pragma unroll
            for (int r8 = 0; r8 < 8; r8++)
                acc[r8] += Qs[(g * 8 + r8) * HDIM + d] * kv;
        }
        #pragma unroll
        for (int r8 = 0; r8 < 8; r8++)
            Ss[(g * 8 + r8) * LSEG + lc + l] = acc[r8] * scale;
        __syncthreads();
    }

    int warp = tid / 32, lane = tid % 32;
    for (int r = warp; r < RT; r += 4) {
        float m = -1e30f;
        for (int i = lane; i < LSEG; i += 32) m = fmaxf(m, Ss[r * LSEG + i]);
        #pragma unroll
        for (int o = 16; o; o >>= 1) m = fmaxf(m, __shfl_xor_sync(0xffffffffu, m, o));
        float sum = 0.f;
        for (int i = lane; i < LSEG; i += 32) {
            float e = __expf(Ss[r * LSEG + i] - m);
            Ss[r * LSEG + i] = e;
            sum += e;
        }
        #pragma unroll
        for (int o = 16; o; o >>= 1) sum += __shfl_xor_sync(0xffffffffu, sum, o);
        if (lane == 0) rsum[r] = 1.0f / sum;
    }
    __syncthreads();

    int c = tid;
    float oacc[RT];
    #pragma unroll
    for (int r = 0; r < RT; r++) oacc[r] = 0.f;
    const float* vbase = &g_kv[(size_t)(s * LSEG) * KVW + NH * HDIM + h * HDIM + c];
    #pragma unroll 4
    for (int lk = 0; lk < LSEG; lk++) {
        float vv = vbase[(size_t)lk * KVW];
        #pragma unroll
        for (int r = 0; r < RT; r++) oacc[r] += Ss[r * LSEG + lk] * vv;
    }
    #pragma unroll
    for (int r = 0; r < RT; r++) {
        float val = oacc[r] * rsum[r];
        size_t o = (size_t)(q_row0 + r) * DIM + h * HDIM + c;
        __nv_bfloat16 hh = __float2bfloat16(val);
        g_o_hi[o] = hh;
        g_o_lo[o] = __float2bfloat16(val - __bfloat162float(hh));
    }
}

// ---------------- final: residual + rmsnorm ----------------
__global__ void final_kernel(const float* __restrict__ w, float* __restrict__ out) {
    int row = blockIdx.x;
    int tid = threadIdx.x;
    float vals[DIM / 256];
    float local = 0.f;
    #pragma unroll
    for (int i = 0; i < DIM / 256; i++) {
        int d = tid + i * 256;
        float v = g_tmp[(size_t)row * DIM + d] + g_queries[(size_t)row * DIM + d];
        vals[i] = v;
        local += v * v;
    }
    __shared__ float red[256];
    red[tid] = local; __syncthreads();
    for (int st = 128; st > 0; st >>= 1) {
        if (tid < st) red[tid] += red[tid + st];
        __syncthreads();
    }
    float rstd = rsqrtf(red[0] / DIM + EPS);
    #pragma unroll
    for (int i = 0; i < DIM / 256; i++) {
        int d = tid + i * 256;
        out[(size_t)row * DIM + d] = vals[i] * rstd * w[d];
    }
}

// ---------------- launch ----------------
extern "C" void kernel_launch(void* const* d_in, const int* in_sizes, int n_in,
                              void* d_out, int out_size) {
    const float* x      = (const float*)d_in[0];
    const float* attn_w = (const float*)d_in[1];
    const float* wq     = (const float*)d_in[2];
    const float* wkv    = (const float*)d_in[3];
    const float* wo     = (const float*)d_in[4];
    const float* out_w  = (const float*)d_in[5];
    float* out = (float*)d_out;

    float *pq, *pkv, *ptmp;
    __nv_bfloat16 *pah, *pal, *pbkvh, *pbkvl, *pbqh, *pbql, *pboh, *pbol;
    __nv_bfloat16 *pqnh, *pqnl, *poh, *pol;
    cudaGetSymbolAddress((void**)&pq,    g_q);
    cudaGetSymbolAddress((void**)&pkv,   g_kv);
    cudaGetSymbolAddress((void**)&ptmp,  g_tmp);
    cudaGetSymbolAddress((void**)&pah,   g_a_hi);
    cudaGetSymbolAddress((void**)&pal,   g_a_lo);
    cudaGetSymbolAddress((void**)&pbkvh, g_bkv_hi);
    cudaGetSymbolAddress((void**)&pbkvl, g_bkv_lo);
    cudaGetSymbolAddress((void**)&pbqh,  g_bq_hi);
    cudaGetSymbolAddress((void**)&pbql,  g_bq_lo);
    cudaGetSymbolAddress((void**)&pboh,  g_bo_hi);
    cudaGetSymbolAddress((void**)&pbol,  g_bo_lo);
    cudaGetSymbolAddress((void**)&pqnh,  g_qn_hi);
    cudaGetSymbolAddress((void**)&pqnl,  g_qn_lo);
    cudaGetSymbolAddress((void**)&poh,   g_o_hi);
    cudaGetSymbolAddress((void**)&pol,   g_o_lo);

    cudaFuncSetAttribute(attention_kernel,
                         cudaFuncAttributeMaxDynamicSharedMemorySize, (int)ATT_SMEM);
    cudaFuncSetAttribute(gemm3_kernel,
                         cudaFuncAttributeMaxDynamicSharedMemorySize, (int)GEMM_SMEM);

    // weight prep (transpose + hi/lo split)
    split_kernel<<<(size_t)NTOK*DIM/256, 256>>>(x, pah, pal);
    tsplit_kernel<<<dim3(KVW/32, DIM/32), dim3(32,8)>>>(wkv, pbkvh, pbkvl, DIM, KVW);
    tsplit_kernel<<<dim3(DIM/32, DIM/32), dim3(32,8)>>>(wq, pbqh, pbql, DIM, DIM);
    tsplit_kernel<<<dim3(DIM/32, DIM/32), dim3(32,8)>>>(wo, pboh, pbol, DIM, DIM);

    // pooling + attention rmsnorm
    pool_rmsnorm_kernel<<<NQ, 256>>>(x, attn_w);

    // q = qn @ wq : M=2048, N=4096
    gemm3_kernel<<<(NQ/BM)*(DIM/BN), 256, GEMM_SMEM>>>(DIM, NQ/BM, DIM/BN,
                                                       pqnh, pqnl, pbqh, pbql, pq);
    // kv = x @ wkv : M=16384, N=8192
    gemm3_kernel<<<(NTOK/BM)*(KVW/BN), 256, GEMM_SMEM>>>(KVW, NTOK/BM, KVW/BN,
                                                         pah, pal, pbkvh, pbkvl, pkv);
    // attention
    attention_kernel<<<dim3(RQ / RT, NH, SEGN), 128, ATT_SMEM>>>();

    // tmp = o @ wo : M=2048, N=4096
    gemm3_kernel<<<(NQ/BM)*(DIM/BN), 256, GEMM_SMEM>>>(DIM, NQ/BM, DIM/BN,
                                                       poh, pol, pboh, pbol, ptmp);
    // residual + rmsnorm
    final_kernel<<<NQ, 256>>>(out_w, out);
}

// round 4
// speedup vs baseline: 6.0188x; 1.2256x over previous
#include <cuda_runtime.h>
#include <cuda_bf16.h>
#include <math.h>
#include <stdint.h>

// ---------------- problem constants ----------------
#define SEGN   32
#define LSEG   512
#define RQ     64
#define POOLN  8
#define NH     32
#define HDIM   128
#define DIM    4096
#define NQ     (SEGN*RQ)     // 2048
#define NTOK   (SEGN*LSEG)   // 16384
#define KVW    (2*NH*HDIM)   // 8192
#define EPS    1e-5f

// arch-specific feature gate (tcgen05/TMEM need the 'a' target)
#if defined(__CUDA_ARCH_FEAT_SM103_ALL) || defined(__CUDA_ARCH_FEAT_SM100_ALL)
#define TC_OK 1
#else
#define TC_OK 0
#endif

// ---------------- scratch ----------------
__device__ __align__(128) float g_queries[(size_t)NQ*DIM];
__device__ __align__(128) float g_q[(size_t)NQ*DIM];
__device__ __align__(128) float g_kv[(size_t)NTOK*KVW];
__device__ __align__(128) float g_tmp[(size_t)NQ*DIM];

__device__ __align__(128) __nv_bfloat16 g_a_hi[(size_t)NTOK*DIM];
__device__ __align__(128) __nv_bfloat16 g_a_lo[(size_t)NTOK*DIM];
__device__ __align__(128) __nv_bfloat16 g_bkv_hi[(size_t)KVW*DIM];
__device__ __align__(128) __nv_bfloat16 g_bkv_lo[(size_t)KVW*DIM];
__device__ __align__(128) __nv_bfloat16 g_bq_hi[(size_t)DIM*DIM];
__device__ __align__(128) __nv_bfloat16 g_bq_lo[(size_t)DIM*DIM];
__device__ __align__(128) __nv_bfloat16 g_bo_hi[(size_t)DIM*DIM];
__device__ __align__(128) __nv_bfloat16 g_bo_lo[(size_t)DIM*DIM];
__device__ __align__(128) __nv_bfloat16 g_qn_hi[(size_t)NQ*DIM];
__device__ __align__(128) __nv_bfloat16 g_qn_lo[(size_t)NQ*DIM];
__device__ __align__(128) __nv_bfloat16 g_o_hi[(size_t)NQ*DIM];
__device__ __align__(128) __nv_bfloat16 g_o_lo[(size_t)NQ*DIM];

// ---------------- generic helpers ----------------
__device__ __forceinline__ uint32_t s2u(const void* p) {
    return (uint32_t)__cvta_generic_to_shared(p);
}
__device__ __forceinline__ void mbar_init(uint32_t a, uint32_t cnt) {
    asm volatile("mbarrier.init.shared.b64 [%0], %1;" :: "r"(a), "r"(cnt) : "memory");
}
__device__ __forceinline__ void mbar_wait(uint32_t a, uint32_t phase) {
    uint32_t done;
    do {
        asm volatile("{\n\t.reg .pred p;\n\t"
                     "mbarrier.try_wait.parity.shared::cta.b64 p, [%1], %2, 0x989680;\n\t"
                     "selp.b32 %0, 1, 0, p;\n\t}"
                     : "=r"(done) : "r"(a), "r"(phase) : "memory");
    } while (!done);
}
__device__ __forceinline__ void cp_async16(uint32_t dst, const void* src) {
    asm volatile("cp.async.cg.shared.global [%0], [%1], 16;" :: "r"(dst), "l"(src) : "memory");
}
__device__ __forceinline__ void cp_async_arrive(uint32_t bar) {
    asm volatile("cp.async.mbarrier.arrive.noinc.shared::cta.b64 [%0];" :: "r"(bar) : "memory");
}
__device__ __forceinline__ uint32_t swz64(uint32_t off) {
    return off ^ ((off >> 3) & 0x30u);
}

#if TC_OK
// ---------------- tcgen05 helpers ('a' targets only) ----------------
__device__ __forceinline__ void tc_alloc(uint32_t smem_dst, uint32_t ncols) {
    asm volatile("tcgen05.alloc.cta_group::1.sync.aligned.shared::cta.b32 [%0], %1;"
                 :: "r"(smem_dst), "r"(ncols) : "memory");
}
__device__ __forceinline__ void tc_dealloc(uint32_t tmem, uint32_t ncols) {
    asm volatile("tcgen05.relinquish_alloc_permit.cta_group::1.sync.aligned;");
    asm volatile("tcgen05.dealloc.cta_group::1.sync.aligned.b32 %0, %1;" :: "r"(tmem), "r"(ncols));
}
__device__ __forceinline__ void tc_commit(uint32_t bar) {
    asm volatile("tcgen05.commit.cta_group::1.mbarrier::arrive::one.shared::cluster.b64 [%0];"
                 :: "r"(bar) : "memory");
}
__device__ __forceinline__ void tc_mma_f16_ss(uint32_t d, uint64_t ad, uint64_t bd,
                                              uint32_t idesc, uint32_t accum) {
    asm volatile("{\n\t.reg .pred p;\n\t"
                 "setp.ne.u32 p, %4, 0;\n\t"
                 "tcgen05.mma.cta_group::1.kind::f16 [%0], %1, %2, %3, {%5, %5, %5, %5}, p;\n\t}"
                 :: "r"(d), "l"(ad), "l"(bd), "r"(idesc), "r"(accum), "r"(0u) : "memory");
}
__device__ __forceinline__ void tc_fence_after() {
    asm volatile("tcgen05.fence::after_thread_sync;" ::: "memory");
}
__device__ __forceinline__ void fence_proxy_async_s() {
    asm volatile("fence.proxy.async.shared::cta;" ::: "memory");
}
#define LDTM_X32(r, addr) \
    asm volatile("tcgen05.ld.sync.aligned.32x32b.x32.b32 " \
        "{%0, %1, %2, %3, %4, %5, %6, %7, %8, %9, %10, %11, %12, %13, %14, %15, " \
        "%16, %17, %18, %19, %20, %21, %22, %23, %24, %25, %26, %27, %28, %29, %30, %31}, [%32];" \
        : "=r"((r)[0]), "=r"((r)[1]), "=r"((r)[2]), "=r"((r)[3]), \
          "=r"((r)[4]), "=r"((r)[5]), "=r"((r)[6]), "=r"((r)[7]), \
          "=r"((r)[8]), "=r"((r)[9]), "=r"((r)[10]), "=r"((r)[11]), \
          "=r"((r)[12]), "=r"((r)[13]), "=r"((r)[14]), "=r"((r)[15]), \
          "=r"((r)[16]), "=r"((r)[17]), "=r"((r)[18]), "=r"((r)[19]), \
          "=r"((r)[20]), "=r"((r)[21]), "=r"((r)[22]), "=r"((r)[23]), \
          "=r"((r)[24]), "=r"((r)[25]), "=r"((r)[26]), "=r"((r)[27]), \
          "=r"((r)[28]), "=r"((r)[29]), "=r"((r)[30]), "=r"((r)[31]) \
        : "r"(addr))
__device__ __forceinline__ void tc_wait_ld() {
    asm volatile("tcgen05.wait::ld.sync.aligned;" ::: "memory");
}
// SW64 K-major descriptor: layout=4, version=1, SBO=32 (8 rows x 64B), LBO=1
static __device__ __forceinline__ uint64_t make_desc64(uint32_t addr) {
    const uint64_t base = (uint64_t(4) << 61) | (uint64_t(1) << 46) |
                          (uint64_t(32) << 32) | (uint64_t(1) << 16);
    return base | ((uint64_t)(addr >> 4) & 0x3FFFull);
}
#else
// ---------------- mma.sync helper (portable PTX, bare sm_103) ----------------
__device__ __forceinline__ void mma16816(float* c, const uint32_t* a, uint32_t b0, uint32_t b1) {
    asm volatile("mma.sync.aligned.m16n8k16.row.col.f32.bf16.bf16.f32 "
                 "{%0,%1,%2,%3}, {%4,%5,%6,%7}, {%8,%9}, {%0,%1,%2,%3};"
                 : "+f"(c[0]), "+f"(c[1]), "+f"(c[2]), "+f"(c[3])
                 : "r"(a[0]), "r"(a[1]), "r"(a[2]), "r"(a[3]), "r"(b0), "r"(b1));
}
#endif

// ---------------- transpose-split: [Kdim,Ndim] fp32 -> [Ndim,Kdim] bf16 hi/lo ----------------
__global__ void tsplit_kernel(const float* __restrict__ in,
                              __nv_bfloat16* __restrict__ hi,
                              __nv_bfloat16* __restrict__ lo,
                              int Kdim, int Ndim) {
    __shared__ float t[32][33];
    int n0 = blockIdx.x * 32, k0 = blockIdx.y * 32;
    int tx = threadIdx.x, ty = threadIdx.y;
    for (int r = ty; r < 32; r += 8)
        t[r][tx] = in[(size_t)(k0 + r) * Ndim + n0 + tx];
    __syncthreads();
    for (int r = ty; r < 32; r += 8) {
        float a = t[tx][r];
        size_t o = (size_t)(n0 + r) * Kdim + k0 + tx;
        __nv_bfloat16 h = __float2bfloat16(a);
        hi[o] = h;
        lo[o] = __float2bfloat16(a - __bfloat162float(h));
    }
}

// ---------------- fused: x split + pooling + attention rmsnorm ----------------
__global__ void pool_rmsnorm_kernel(const float* __restrict__ x,
                                    const float* __restrict__ w) {
    int row = blockIdx.x;          // query index
    int tid = threadIdx.x;         // 256
    const float* base = x + (size_t)row * POOLN * DIM;
    float local = 0.f;
    for (int d = tid; d < DIM; d += 256) {
        float s = 0.f;
        #pragma unroll
        for (int p = 0; p < POOLN; p++) {
            float v = base[(size_t)p*DIM + d];
            __nv_bfloat16 h = __float2bfloat16(v);
            size_t o = (size_t)(row * POOLN + p) * DIM + d;
            g_a_hi[o] = h;
            g_a_lo[o] = __float2bfloat16(v - __bfloat162float(h));
            s += v;
        }
        s *= (1.0f / POOLN);
        g_queries[(size_t)row*DIM + d] = s;
        local += s * s;
    }
    __shared__ float red[256];
    red[tid] = local; __syncthreads();
    for (int st = 128; st > 0; st >>= 1) {
        if (tid < st) red[tid] += red[tid + st];
        __syncthreads();
    }
    float rstd = rsqrtf(red[0] / DIM + EPS);
    for (int d = tid; d < DIM; d += 256) {
        float v = g_queries[(size_t)row*DIM + d] * rstd * w[d];
        __nv_bfloat16 h = __float2bfloat16(v);
        g_qn_hi[(size_t)row*DIM + d] = h;
        g_qn_lo[(size_t)row*DIM + d] = __float2bfloat16(v - __bfloat162float(h));
    }
}

// ---------------- bf16x3 GEMM: C[M,N] = A[M,K] @ B[N,K]^T, K=4096 ----------------
// 256x256 tiles, K-chunk 32, SW64 smem (64B rows), 3 stages, 2 cg1 MMAs per chunk half.
#define BM 256
#define BN 256
#define GK 4096
#define KITERS (GK/32)               // 128
#define A_TILE_B 8192u               // 128 rows x 64B
#define B_TILE_B 16384u              // 256 rows x 64B
#define STAGE_BYTES (4u*A_TILE_B + 2u*B_TILE_B)   // 65536
#define NSTAGE 3
#define CHUNKS 4096                  // STAGE_BYTES/16
#define GEMM_SMEM (NSTAGE*STAGE_BYTES + 1024)

__global__ __launch_bounds__(256, 1)
void gemm3_kernel(int N, int nbm, int nbn,
                  const __nv_bfloat16* __restrict__ Ah,
                  const __nv_bfloat16* __restrict__ Al,
                  const __nv_bfloat16* __restrict__ Bh,
                  const __nv_bfloat16* __restrict__ Bl,
                  float* __restrict__ C) {
    extern __shared__ char smraw[];
    char* smp = (char*)((((uintptr_t)smraw) + 1023) & ~(uintptr_t)1023);
    int tid = threadIdx.x;

    // grouped tile mapping (GROUP_M = 16)
    const int GM = 16;
    int bid = blockIdx.x;
    int group = bid / (GM * nbn);
    int first_m = group * GM;
    int gsz = min(nbm - first_m, GM);
    int pm = first_m + (bid % gsz);
    int pn = (bid % (GM * nbn)) / gsz;
    int m0 = pm * BM, n0 = pn * BN;

#if TC_OK
    uint32_t sb0 = s2u(smp);
    __shared__ __align__(8) unsigned long long full_b[NSTAGE], empty_b[NSTAGE], fin_b;
    __shared__ uint32_t tmem_ptr_sh;

    uint32_t full_a[NSTAGE], empty_a[NSTAGE], fin_a;
    #pragma unroll
    for (int i = 0; i < NSTAGE; i++) {
        full_a[i] = s2u(&full_b[i]);
        empty_a[i] = s2u(&empty_b[i]);
    }
    fin_a = s2u(&fin_b);

    if (tid < 32) tc_alloc(s2u(&tmem_ptr_sh), 512);
    if (tid == 0) {
        #pragma unroll
        for (int i = 0; i < NSTAGE; i++) {
            mbar_init(full_a[i], 224);
            mbar_init(empty_a[i], 1);
        }
        mbar_init(fin_a, 1);
    }
    __syncthreads();
    uint32_t tmem = tmem_ptr_sh;

    const uint32_t idesc = (1u<<4) | (1u<<7) | (1u<<10) | ((BN/8)<<17) | (8u<<24);

    if (tid >= 32) {
        // ------- producers (224 threads) -------
        for (int it = 0; it < KITERS; it++) {
            int s = it % NSTAGE;
            uint32_t ph = ((it / NSTAGE) & 1) ^ 1u;
            mbar_wait(empty_a[s], ph);
            int k0 = it * 32;
            uint32_t sb = sb0 + s * STAGE_BYTES;
            for (int i = tid - 32; i < CHUNKS; i += 224) {
                const __nv_bfloat16* src;
                uint32_t dst;
                if (i < 2048) {
                    // A tiles: [A0h, A0l, A1h, A1l], 512 chunks each (128 rows x 4)
                    int tile = i >> 9;
                    int j = i & 511;
                    int r = j >> 2, c = j & 3;
                    dst = sb + tile * A_TILE_B + swz64(r * 64 + c * 16);
                    int row = m0 + ((tile >> 1) << 7) + r;
                    src = ((tile & 1) == 0 ? Ah : Al) + (size_t)row * GK + k0 + c * 8;
                } else {
                    // B tiles: [Bh, Bl], 1024 chunks each (256 rows x 4)
                    int j = i - 2048;
                    int hi = (j < 1024);
                    j &= 1023;
                    int r = j >> 2, c = j & 3;
                    dst = sb + 4u*A_TILE_B + (hi ? 0u : B_TILE_B) + swz64(r * 64 + c * 16);
                    src = (hi ? Bh : Bl) + (size_t)(n0 + r) * GK + k0 + c * 8;
                }
                cp_async16(dst, src);
            }
            cp_async_arrive(full_a[s]);
        }
    } else if (tid == 0) {
        // ------- MMA issuer -------
        for (int it = 0; it < KITERS; it++) {
            int s = it % NSTAGE;
            uint32_t ph = (it / NSTAGE) & 1;
            mbar_wait(full_a[s], ph);
            fence_proxy_async_s();
            uint32_t sb = sb0 + s * STAGE_BYTES;
            uint64_t a0h = make_desc64(sb);
            uint64_t a0l = make_desc64(sb + A_TILE_B);
            uint64_t a1h = make_desc64(sb + 2u*A_TILE_B);
            uint64_t a1l = make_desc64(sb + 3u*A_TILE_B);
            uint64_t bh  = make_desc64(sb + 4u*A_TILE_B);
            uint64_t bl  = make_desc64(sb + 4u*A_TILE_B + B_TILE_B);
            #pragma unroll
            for (int ks = 0; ks < 2; ks++) {
                uint32_t acc = (it > 0 || ks > 0) ? 1u : 0u;
                uint64_t o = ks * 2;
                tc_mma_f16_ss(tmem,       a0h + o, bh + o, idesc, acc);
                tc_mma_f16_ss(tmem + 256, a1h + o, bh + o, idesc, acc);
                tc_mma_f16_ss(tmem,       a0h + o, bl + o, idesc, 1u);
                tc_mma_f16_ss(tmem + 256, a1h + o, bl + o, idesc, 1u);
                tc_mma_f16_ss(tmem,       a0l + o, bh + o, idesc, 1u);
                tc_mma_f16_ss(tmem + 256, a1l + o, bh + o, idesc, 1u);
            }
            tc_commit(empty_a[s]);
        }
        tc_commit(fin_a);
    }

    __syncthreads();
    mbar_wait(fin_a, 0);
    tc_fence_after();

    // epilogue: two M=128 halves; TMEM -> smem staging -> coalesced stores
    float* stg = (float*)smp;
    int w = tid >> 5, lane = tid & 31;
    #pragma unroll
    for (int half = 0; half < 2; half++) {
        if (w < 4) {
            for (int ch = 0; ch < 8; ch++) {
                uint32_t r[32];
                LDTM_X32(r, tmem + half * 256 + ch * 32);
                tc_wait_ld();
                #pragma unroll
                for (int j = 0; j < 32; j++)
                    stg[(size_t)(w * 32 + lane) * 260 + ch * 32 + j] = __uint_as_float(r[j]);
            }
        }
        __syncthreads();
        int c4 = (tid & 63) * 4;
        for (int rr = tid >> 6; rr < 128; rr += 4) {
            float4 v = *(float4*)&stg[(size_t)rr * 260 + c4];
            *(float4*)&C[(size_t)(m0 + half * 128 + rr) * N + n0 + c4] = v;
        }
        __syncthreads();
    }
    if (tid < 32) tc_dealloc(tmem, 512);
#else
    // ======== mma.sync bf16x3 fallback (bare sm_103; never selected on GB300) ========
    __nv_bfloat16* sAh = (__nv_bfloat16*)smp;
    __nv_bfloat16* sAl = sAh + 128 * 40;
    __nv_bfloat16* sBh = sAl + 128 * 40;
    __nv_bfloat16* sBl = sBh + 128 * 40;

    int lane = tid & 31, w = tid >> 5;
    int wm = w & 3, wn = w >> 2;

    for (int mh = 0; mh < 2; mh++)
    for (int nh = 0; nh < 2; nh++) {
        int m0h = m0 + mh * 128;
        int n0h = n0 + nh * 128;
        float acc[2][8][4];
        #pragma unroll
        for (int mi = 0; mi < 2; mi++)
            #pragma unroll
            for (int ni = 0; ni < 8; ni++)
                #pragma unroll
                for (int j = 0; j < 4; j++) acc[mi][ni][j] = 0.f;

        for (int k0 = 0; k0 < GK; k0 += 32) {
            __syncthreads();
            for (int cid = tid; cid < 512; cid += 256) {
                int r = cid >> 2, c = cid & 3;
                *(uint4*)&sAh[r*40 + c*8] = *(const uint4*)&Ah[(size_t)(m0h+r)*GK + k0 + c*8];
                *(uint4*)&sAl[r*40 + c*8] = *(const uint4*)&Al[(size_t)(m0h+r)*GK + k0 + c*8];
                *(uint4*)&sBh[r*40 + c*8] = *(const uint4*)&Bh[(size_t)(n0h+r)*GK + k0 + c*8];
                *(uint4*)&sBl[r*40 + c*8] = *(const uint4*)&Bl[(size_t)(n0h+r)*GK + k0 + c*8];
            }
            __syncthreads();
            #pragma unroll
            for (int ks = 0; ks < 2; ks++) {
                int kc = (lane & 3) * 2 + ks * 16;
                uint32_t ah[2][4], al[2][4];
                #pragma unroll
                for (int mi = 0; mi < 2; mi++) {
                    int r = wm * 32 + mi * 16 + (lane >> 2);
                    ah[mi][0] = *(uint32_t*)&sAh[r*40 + kc];
                    ah[mi][1] = *(uint32_t*)&sAh[(r+8)*40 + kc];
                    ah[mi][2] = *(uint32_t*)&sAh[r*40 + kc + 8];
                    ah[mi][3] = *(uint32_t*)&sAh[(r+8)*40 + kc + 8];
                    al[mi][0] = *(uint32_t*)&sAl[r*40 + kc];
                    al[mi][1] = *(uint32_t*)&sAl[(r+8)*40 + kc];
                    al[mi][2] = *(uint32_t*)&sAl[r*40 + kc + 8];
                    al[mi][3] = *(uint32_t*)&sAl[(r+8)*40 + kc + 8];
                }
                #pragma unroll
                for (int ni = 0; ni < 4; ni++) {
                    int nr = wn * 64 + ni * 8 + (lane >> 2);
                    uint32_t bh0 = *(uint32_t*)&sBh[nr*40 + kc];
                    uint32_t bh1 = *(uint32_t*)&sBh[nr*40 + kc + 8];
                    uint32_t bl0 = *(uint32_t*)&sBl[nr*40 + kc];
                    uint32_t bl1 = *(uint32_t*)&sBl[nr*40 + kc + 8];
                    #pragma unroll
                    for (int mi = 0; mi < 2; mi++) {
                        mma16816(acc[mi][ni], ah[mi], bh0, bh1);
                        mma16816(acc[mi][ni], ah[mi], bl0, bl1);
                        mma16816(acc[mi][ni], al[mi], bh0, bh1);
                    }
                }
            }
        }
        #pragma unroll
        for (int mi = 0; mi < 2; mi++)
            #pragma unroll
            for (int ni = 0; ni < 4; ni++) {
                int r = m0h + wm * 32 + mi * 16 + (lane >> 2);
                int c = n0h + wn * 64 + ni * 8 + (lane & 3) * 2;
                *(float2*)&C[(size_t)r * N + c] = make_float2(acc[mi][ni][0], acc[mi][ni][1]);
                *(float2*)&C[(size_t)(r+8) * N + c] = make_float2(acc[mi][ni][2], acc[mi][ni][3]);
            }
    }
#endif
}

// ---------------- attention (emits bf16 hi/lo output) ----------------
#define RT  16
#define KC  64
#define ATT_SMEM ((RT*HDIM + KC*(HDIM+1) + RT*LSEG + RT) * sizeof(float))

__global__ __launch_bounds__(128)
void attention_kernel() {
    extern __shared__ float sm[];
    float* Qs   = sm;
    float* Ks   = Qs + RT * HDIM;
    float* Ss   = Ks + KC * (HDIM + 1);
    float* rsum = Ss + RT * LSEG;

    int rt = blockIdx.x;
    int h  = blockIdx.y;
    int s  = blockIdx.z;
    int tid = threadIdx.x;
    int q_row0 = s * RQ + rt * RT;

    for (int i = tid; i < RT * HDIM; i += 128) {
        int r = i / HDIM, d = i % HDIM;
        Qs[r * HDIM + d] = g_q[(size_t)(q_row0 + r) * DIM + h * HDIM + d];
    }
    const float scale = rsqrtf((float)HDIM);
    int g = tid / KC;
    int l = tid % KC;
    __syncthreads();

    for (int lc = 0; lc < LSEG; lc += KC) {
        for (int i = tid; i < KC * (HDIM / 4); i += 128) {
            int kr = i / (HDIM / 4);
            int c4 = i % (HDIM / 4);
            float4 v = *reinterpret_cast<const float4*>(
                &g_kv[(size_t)(s * LSEG + lc + kr) * KVW + h * HDIM + c4 * 4]);
            float* dst = &Ks[kr * (HDIM + 1) + c4 * 4];
            dst[0] = v.x; dst[1] = v.y; dst[2] = v.z; dst[3] = v.w;
        }
        __syncthreads();
        float acc[8];
        #pragma unroll
        for (int r8 = 0; r8 < 8; r8++) acc[r8] = 0.f;
        #pragma unroll 4
        for (int d = 0; d < HDIM; d++) {
            float kv = Ks[l * (HDIM + 1) + d];
            #pragma unroll
            for (int r8 = 0; r8 < 8; r8++)
                acc[r8] += Qs[(g * 8 + r8) * HDIM + d] * kv;
        }
        #pragma unroll
        for (int r8 = 0; r8 < 8; r8++)
            Ss[(g * 8 + r8) * LSEG + lc + l] = acc[r8] * scale;
        __syncthreads();
    }

    int warp = tid / 32, lane = tid % 32;
    for (int r = warp; r < RT; r += 4) {
        float m = -1e30f;
        for (int i = lane; i < LSEG; i += 32) m = fmaxf(m, Ss[r * LSEG + i]);
        #pragma unroll
        for (int o = 16; o; o >>= 1) m = fmaxf(m, __shfl_xor_sync(0xffffffffu, m, o));
        float sum = 0.f;
        for (int i = lane; i < LSEG; i += 32) {
            float e = __expf(Ss[r * LSEG + i] - m);
            Ss[r * LSEG + i] = e;
            sum += e;
        }
        #pragma unroll
        for (int o = 16; o; o >>= 1) sum += __shfl_xor_sync(0xffffffffu, sum, o);
        if (lane == 0) rsum[r] = 1.0f / sum;
    }
    __syncthreads();

    int c = tid;
    float oacc[RT];
    #pragma unroll
    for (int r = 0; r < RT; r++) oacc[r] = 0.f;
    const float* vbase = &g_kv[(size_t)(s * LSEG) * KVW + NH * HDIM + h * HDIM + c];
    #pragma unroll 4
    for (int lk = 0; lk < LSEG; lk++) {
        float vv = vbase[(size_t)lk * KVW];
        #pragma unroll
        for (int r = 0; r < RT; r++) oacc[r] += Ss[r * LSEG + lk] * vv;
    }
    #pragma unroll
    for (int r = 0; r < RT; r++) {
        float val = oacc[r] * rsum[r];
        size_t o = (size_t)(q_row0 + r) * DIM + h * HDIM + c;
        __nv_bfloat16 hh = __float2bfloat16(val);
        g_o_hi[o] = hh;
        g_o_lo[o] = __float2bfloat16(val - __bfloat162float(hh));
    }
}

// ---------------- final: residual + rmsnorm ----------------
__global__ void final_kernel(const float* __restrict__ w, float* __restrict__ out) {
    int row = blockIdx.x;
    int tid = threadIdx.x;
    float vals[DIM / 256];
    float local = 0.f;
    #pragma unroll
    for (int i = 0; i < DIM / 256; i++) {
        int d = tid + i * 256;
        float v = g_tmp[(size_t)row * DIM + d] + g_queries[(size_t)row * DIM + d];
        vals[i] = v;
        local += v * v;
    }
    __shared__ float red[256];
    red[tid] = local; __syncthreads();
    for (int st = 128; st > 0; st >>= 1) {
        if (tid < st) red[tid] += red[tid + st];
        __syncthreads();
    }
    float rstd = rsqrtf(red[0] / DIM + EPS);
    #pragma unroll
    for (int i = 0; i < DIM / 256; i++) {
        int d = tid + i * 256;
        out[(size_t)row * DIM + d] = vals[i] * rstd * w[d];
    }
}

// ---------------- launch ----------------
extern "C" void kernel_launch(void* const* d_in, const int* in_sizes, int n_in,
                              void* d_out, int out_size) {
    const float* x      = (const float*)d_in[0];
    const float* attn_w = (const float*)d_in[1];
    const float* wq     = (const float*)d_in[2];
    const float* wkv    = (const float*)d_in[3];
    const float* wo     = (const float*)d_in[4];
    const float* out_w  = (const float*)d_in[5];
    float* out = (float*)d_out;

    float *pq, *pkv, *ptmp;
    __nv_bfloat16 *pah, *pal, *pbkvh, *pbkvl, *pbqh, *pbql, *pboh, *pbol;
    __nv_bfloat16 *pqnh, *pqnl, *poh, *pol;
    cudaGetSymbolAddress((void**)&pq,    g_q);
    cudaGetSymbolAddress((void**)&pkv,   g_kv);
    cudaGetSymbolAddress((void**)&ptmp,  g_tmp);
    cudaGetSymbolAddress((void**)&pah,   g_a_hi);
    cudaGetSymbolAddress((void**)&pal,   g_a_lo);
    cudaGetSymbolAddress((void**)&pbkvh, g_bkv_hi);
    cudaGetSymbolAddress((void**)&pbkvl, g_bkv_lo);
    cudaGetSymbolAddress((void**)&pbqh,  g_bq_hi);
    cudaGetSymbolAddress((void**)&pbql,  g_bq_lo);
    cudaGetSymbolAddress((void**)&pboh,  g_bo_hi);
    cudaGetSymbolAddress((void**)&pbol,  g_bo_lo);
    cudaGetSymbolAddress((void**)&pqnh,  g_qn_hi);
    cudaGetSymbolAddress((void**)&pqnl,  g_qn_lo);
    cudaGetSymbolAddress((void**)&poh,   g_o_hi);
    cudaGetSymbolAddress((void**)&pol,   g_o_lo);

    cudaFuncSetAttribute(attention_kernel,
                         cudaFuncAttributeMaxDynamicSharedMemorySize, (int)ATT_SMEM);
    cudaFuncSetAttribute(gemm3_kernel,
                         cudaFuncAttributeMaxDynamicSharedMemorySize, (int)GEMM_SMEM);

    // weight prep (transpose + hi/lo split)
    tsplit_kernel<<<dim3(KVW/32, DIM/32), dim3(32,8)>>>(wkv, pbkvh, pbkvl, DIM, KVW);
    tsplit_kernel<<<dim3(DIM/32, DIM/32), dim3(32,8)>>>(wq, pbqh, pbql, DIM, DIM);
    tsplit_kernel<<<dim3(DIM/32, DIM/32), dim3(32,8)>>>(wo, pboh, pbol, DIM, DIM);

    // fused x-split + pooling + attention rmsnorm
    pool_rmsnorm_kernel<<<NQ, 256>>>(x, attn_w);

    // q = qn @ wq : M=2048, N=4096 -> 8x16 = 128 CTAs
    gemm3_kernel<<<(NQ/BM)*(DIM/BN), 256, GEMM_SMEM>>>(DIM, NQ/BM, DIM/BN,
                                                       pqnh, pqnl, pbqh, pbql, pq);
    // kv = x @ wkv : M=16384, N=8192 -> 64x32 = 2048 CTAs
    gemm3_kernel<<<(NTOK/BM)*(KVW/BN), 256, GEMM_SMEM>>>(KVW, NTOK/BM, KVW/BN,
                                                         pah, pal, pbkvh, pbkvl, pkv);
    // attention
    attention_kernel<<<dim3(RQ / RT, NH, SEGN), 128, ATT_SMEM>>>();

    // tmp = o @ wo : M=2048, N=4096
    gemm3_kernel<<<(NQ/BM)*(DIM/BN), 256, GEMM_SMEM>>>(DIM, NQ/BM, DIM/BN,
                                                       poh, pol, pboh, pbol, ptmp);
    // residual + rmsnorm
    final_kernel<<<NQ, 256>>>(out_w, out);
}

// round 5
// speedup vs baseline: 8.0955x; 1.3450x over previous
#include <cuda_runtime.h>
#include <cuda.h>
#include <cuda_bf16.h>
#include <math.h>
#include <stdint.h>

// ---------------- problem constants ----------------
#define SEGN   32
#define LSEG   512
#define RQ     64
#define POOLN  8
#define NH     32
#define HDIM   128
#define DIM    4096
#define NQ     (SEGN*RQ)     // 2048
#define NTOK   (SEGN*LSEG)   // 16384
#define KVW    (2*NH*HDIM)   // 8192
#define EPS    1e-5f

// arch-specific feature gate (tcgen05/TMEM need the 'a' target)
#if defined(__CUDA_ARCH_FEAT_SM103_ALL) || defined(__CUDA_ARCH_FEAT_SM100_ALL)
#define TC_OK 1
#else
#define TC_OK 0
#endif

// ---------------- scratch ----------------
__device__ __align__(128) float g_queries[(size_t)NQ*DIM];
__device__ __align__(128) float g_q[(size_t)NQ*DIM];
__device__ __align__(128) float g_kv[(size_t)NTOK*KVW];
__device__ __align__(128) float g_tmp[(size_t)NQ*DIM];

__device__ __align__(128) __nv_bfloat16 g_a_hi[(size_t)NTOK*DIM];
__device__ __align__(128) __nv_bfloat16 g_a_lo[(size_t)NTOK*DIM];
__device__ __align__(128) __nv_bfloat16 g_bkv_hi[(size_t)KVW*DIM];
__device__ __align__(128) __nv_bfloat16 g_bkv_lo[(size_t)KVW*DIM];
__device__ __align__(128) __nv_bfloat16 g_bq_hi[(size_t)DIM*DIM];
__device__ __align__(128) __nv_bfloat16 g_bq_lo[(size_t)DIM*DIM];
__device__ __align__(128) __nv_bfloat16 g_bo_hi[(size_t)DIM*DIM];
__device__ __align__(128) __nv_bfloat16 g_bo_lo[(size_t)DIM*DIM];
__device__ __align__(128) __nv_bfloat16 g_qn_hi[(size_t)NQ*DIM];
__device__ __align__(128) __nv_bfloat16 g_qn_lo[(size_t)NQ*DIM];
__device__ __align__(128) __nv_bfloat16 g_o_hi[(size_t)NQ*DIM];
__device__ __align__(128) __nv_bfloat16 g_o_lo[(size_t)NQ*DIM];

// ---------------- generic helpers ----------------
__device__ __forceinline__ uint32_t s2u(const void* p) {
    return (uint32_t)__cvta_generic_to_shared(p);
}
__device__ __forceinline__ void mbar_init(uint32_t a, uint32_t cnt) {
    asm volatile("mbarrier.init.shared.b64 [%0], %1;" :: "r"(a), "r"(cnt) : "memory");
}
__device__ __forceinline__ void mbar_wait(uint32_t a, uint32_t phase) {
    uint32_t done;
    do {
        asm volatile("{\n\t.reg .pred p;\n\t"
                     "mbarrier.try_wait.parity.shared::cta.b64 p, [%1], %2, 0x989680;\n\t"
                     "selp.b32 %0, 1, 0, p;\n\t}"
                     : "=r"(done) : "r"(a), "r"(phase) : "memory");
    } while (!done);
}
__device__ __forceinline__ void mbar_expect_tx(uint32_t a, uint32_t bytes) {
    asm volatile("mbarrier.arrive.expect_tx.shared.b64 _, [%0], %1;"
                 :: "r"(a), "r"(bytes) : "memory");
}
__device__ __forceinline__ void tma_load_2d(uint32_t dst, const void* map,
                                            int cx, int cy, uint32_t bar) {
    asm volatile("cp.async.bulk.tensor.2d.shared::cta.global.tile.mbarrier::complete_tx::bytes "
                 "[%0], [%1, {%2, %3}], [%4];"
                 :: "r"(dst), "l"(map), "r"(cx), "r"(cy), "r"(bar) : "memory");
}

#if TC_OK
// ---------------- tcgen05 helpers ('a' targets only) ----------------
__device__ __forceinline__ void tc_alloc(uint32_t smem_dst, uint32_t ncols) {
    asm volatile("tcgen05.alloc.cta_group::1.sync.aligned.shared::cta.b32 [%0], %1;"
                 :: "r"(smem_dst), "r"(ncols) : "memory");
}
__device__ __forceinline__ void tc_dealloc(uint32_t tmem, uint32_t ncols) {
    asm volatile("tcgen05.relinquish_alloc_permit.cta_group::1.sync.aligned;");
    asm volatile("tcgen05.dealloc.cta_group::1.sync.aligned.b32 %0, %1;" :: "r"(tmem), "r"(ncols));
}
__device__ __forceinline__ void tc_commit(uint32_t bar) {
    asm volatile("tcgen05.commit.cta_group::1.mbarrier::arrive::one.shared::cluster.b64 [%0];"
                 :: "r"(bar) : "memory");
}
__device__ __forceinline__ void tc_mma_f16_ss(uint32_t d, uint64_t ad, uint64_t bd,
                                              uint32_t idesc, uint32_t accum) {
    asm volatile("{\n\t.reg .pred p;\n\t"
                 "setp.ne.u32 p, %4, 0;\n\t"
                 "tcgen05.mma.cta_group::1.kind::f16 [%0], %1, %2, %3, {%5, %5, %5, %5}, p;\n\t}"
                 :: "r"(d), "l"(ad), "l"(bd), "r"(idesc), "r"(accum), "r"(0u) : "memory");
}
__device__ __forceinline__ void tc_fence_after() {
    asm volatile("tcgen05.fence::after_thread_sync;" ::: "memory");
}
#define LDTM_X32(r, addr) \
    asm volatile("tcgen05.ld.sync.aligned.32x32b.x32.b32 " \
        "{%0, %1, %2, %3, %4, %5, %6, %7, %8, %9, %10, %11, %12, %13, %14, %15, " \
        "%16, %17, %18, %19, %20, %21, %22, %23, %24, %25, %26, %27, %28, %29, %30, %31}, [%32];" \
        : "=r"((r)[0]), "=r"((r)[1]), "=r"((r)[2]), "=r"((r)[3]), \
          "=r"((r)[4]), "=r"((r)[5]), "=r"((r)[6]), "=r"((r)[7]), \
          "=r"((r)[8]), "=r"((r)[9]), "=r"((r)[10]), "=r"((r)[11]), \
          "=r"((r)[12]), "=r"((r)[13]), "=r"((r)[14]), "=r"((r)[15]), \
          "=r"((r)[16]), "=r"((r)[17]), "=r"((r)[18]), "=r"((r)[19]), \
          "=r"((r)[20]), "=r"((r)[21]), "=r"((r)[22]), "=r"((r)[23]), \
          "=r"((r)[24]), "=r"((r)[25]), "=r"((r)[26]), "=r"((r)[27]), \
          "=r"((r)[28]), "=r"((r)[29]), "=r"((r)[30]), "=r"((r)[31]) \
        : "r"(addr))
__device__ __forceinline__ void tc_wait_ld() {
    asm volatile("tcgen05.wait::ld.sync.aligned;" ::: "memory");
}
// SW64 K-major descriptor: layout=4, version=1, SBO=32 (8 rows x 64B), LBO=1
static __device__ __forceinline__ uint64_t make_desc64(uint32_t addr) {
    const uint64_t base = (uint64_t(4) << 61) | (uint64_t(1) << 46) |
                          (uint64_t(32) << 32) | (uint64_t(1) << 16);
    return base | ((uint64_t)(addr >> 4) & 0x3FFFull);
}
#else
// ---------------- mma.sync helper (portable PTX, bare sm_103) ----------------
__device__ __forceinline__ void mma16816(float* c, const uint32_t* a, uint32_t b0, uint32_t b1) {
    asm volatile("mma.sync.aligned.m16n8k16.row.col.f32.bf16.bf16.f32 "
                 "{%0,%1,%2,%3}, {%4,%5,%6,%7}, {%8,%9}, {%0,%1,%2,%3};"
                 : "+f"(c[0]), "+f"(c[1]), "+f"(c[2]), "+f"(c[3])
                 : "r"(a[0]), "r"(a[1]), "r"(a[2]), "r"(a[3]), "r"(b0), "r"(b1));
}
#endif

// ---------------- transpose-split: [Kdim,Ndim] fp32 -> [Ndim,Kdim] bf16 hi/lo ----------------
__global__ void tsplit_kernel(const float* __restrict__ in,
                              __nv_bfloat16* __restrict__ hi,
                              __nv_bfloat16* __restrict__ lo,
                              int Kdim, int Ndim) {
    __shared__ float t[32][33];
    int n0 = blockIdx.x * 32, k0 = blockIdx.y * 32;
    int tx = threadIdx.x, ty = threadIdx.y;
    for (int r = ty; r < 32; r += 8)
        t[r][tx] = in[(size_t)(k0 + r) * Ndim + n0 + tx];
    __syncthreads();
    for (int r = ty; r < 32; r += 8) {
        float a = t[tx][r];
        size_t o = (size_t)(n0 + r) * Kdim + k0 + tx;
        __nv_bfloat16 h = __float2bfloat16(a);
        hi[o] = h;
        lo[o] = __float2bfloat16(a - __bfloat162float(h));
    }
}

// ---------------- fused: x split + pooling + attention rmsnorm ----------------
__global__ void pool_rmsnorm_kernel(const float* __restrict__ x,
                                    const float* __restrict__ w) {
    int row = blockIdx.x;
    int tid = threadIdx.x;
    const float* base = x + (size_t)row * POOLN * DIM;
    float local = 0.f;
    for (int d = tid; d < DIM; d += 256) {
        float s = 0.f;
        #pragma unroll
        for (int p = 0; p < POOLN; p++) {
            float v = base[(size_t)p*DIM + d];
            __nv_bfloat16 h = __float2bfloat16(v);
            size_t o = (size_t)(row * POOLN + p) * DIM + d;
            g_a_hi[o] = h;
            g_a_lo[o] = __float2bfloat16(v - __bfloat162float(h));
            s += v;
        }
        s *= (1.0f / POOLN);
        g_queries[(size_t)row*DIM + d] = s;
        local += s * s;
    }
    __shared__ float red[256];
    red[tid] = local; __syncthreads();
    for (int st = 128; st > 0; st >>= 1) {
        if (tid < st) red[tid] += red[tid + st];
        __syncthreads();
    }
    float rstd = rsqrtf(red[0] / DIM + EPS);
    for (int d = tid; d < DIM; d += 256) {
        float v = g_queries[(size_t)row*DIM + d] * rstd * w[d];
        __nv_bfloat16 h = __float2bfloat16(v);
        g_qn_hi[(size_t)row*DIM + d] = h;
        g_qn_lo[(size_t)row*DIM + d] = __float2bfloat16(v - __bfloat162float(h));
    }
}

// ---------------- bf16x3 GEMM: C[M,N] = A[M,K] @ B[N,K]^T, K=4096 ----------------
// 256x256 tiles, K-chunk 32, SW64 smem, 3 stages, TMA producer (1 thread).
#define BM 256
#define BN 256
#define GK 4096
#define KITERS (GK/32)               // 128
#define A_TILE_B 8192u               // 128 rows x 64B
#define B_TILE_B 16384u              // 256 rows x 64B
#define STAGE_BYTES (4u*A_TILE_B + 2u*B_TILE_B)   // 65536
#define NSTAGE 3
#define GEMM_SMEM (NSTAGE*STAGE_BYTES + 1024)

__global__ __launch_bounds__(256, 1)
void gemm3_kernel(int N, int nbm, int nbn,
                  const __grid_constant__ CUtensorMap mAh,
                  const __grid_constant__ CUtensorMap mAl,
                  const __grid_constant__ CUtensorMap mBh,
                  const __grid_constant__ CUtensorMap mBl,
                  const __nv_bfloat16* __restrict__ Ah,
                  const __nv_bfloat16* __restrict__ Al,
                  const __nv_bfloat16* __restrict__ Bh,
                  const __nv_bfloat16* __restrict__ Bl,
                  float* __restrict__ C) {
    extern __shared__ char smraw[];
    char* smp = (char*)((((uintptr_t)smraw) + 1023) & ~(uintptr_t)1023);
    int tid = threadIdx.x;

    // grouped tile mapping (GROUP_M = 16)
    const int GM = 16;
    int bid = blockIdx.x;
    int group = bid / (GM * nbn);
    int first_m = group * GM;
    int gsz = min(nbm - first_m, GM);
    int pm = first_m + (bid % gsz);
    int pn = (bid % (GM * nbn)) / gsz;
    int m0 = pm * BM, n0 = pn * BN;

#if TC_OK
    uint32_t sb0 = s2u(smp);
    __shared__ __align__(8) unsigned long long full_b[NSTAGE], empty_b[NSTAGE], fin_b;
    __shared__ uint32_t tmem_ptr_sh;

    uint32_t full_a[NSTAGE], empty_a[NSTAGE], fin_a;
    #pragma unroll
    for (int i = 0; i < NSTAGE; i++) {
        full_a[i] = s2u(&full_b[i]);
        empty_a[i] = s2u(&empty_b[i]);
    }
    fin_a = s2u(&fin_b);

    if (tid < 32) tc_alloc(s2u(&tmem_ptr_sh), 512);
    if (tid == 0) {
        #pragma unroll
        for (int i = 0; i < NSTAGE; i++) {
            mbar_init(full_a[i], 1);
            mbar_init(empty_a[i], 1);
        }
        mbar_init(fin_a, 1);
    }
    __syncthreads();
    uint32_t tmem = tmem_ptr_sh;

    const uint32_t idesc = (1u<<4) | (1u<<7) | (1u<<10) | ((BN/8)<<17) | (8u<<24);

    if (tid == 32) {
        // ------- TMA producer (single thread) -------
        for (int it = 0; it < KITERS; it++) {
            int s = it % NSTAGE;
            uint32_t ph = ((it / NSTAGE) & 1) ^ 1u;
            mbar_wait(empty_a[s], ph);
            int k0 = it * 32;
            uint32_t sb = sb0 + s * STAGE_BYTES;
            uint32_t bar = full_a[s];
            mbar_expect_tx(bar, STAGE_BYTES);
            tma_load_2d(sb,                          &mAh, k0, m0,       bar);
            tma_load_2d(sb + A_TILE_B,               &mAl, k0, m0,       bar);
            tma_load_2d(sb + 2u*A_TILE_B,            &mAh, k0, m0 + 128, bar);
            tma_load_2d(sb + 3u*A_TILE_B,            &mAl, k0, m0 + 128, bar);
            tma_load_2d(sb + 4u*A_TILE_B,            &mBh, k0, n0,       bar);
            tma_load_2d(sb + 4u*A_TILE_B + B_TILE_B, &mBl, k0, n0,       bar);
        }
    } else if (tid == 0) {
        // ------- MMA issuer -------
        for (int it = 0; it < KITERS; it++) {
            int s = it % NSTAGE;
            uint32_t ph = (it / NSTAGE) & 1;
            mbar_wait(full_a[s], ph);
            uint32_t sb = sb0 + s * STAGE_BYTES;
            uint64_t a0h = make_desc64(sb);
            uint64_t a0l = make_desc64(sb + A_TILE_B);
            uint64_t a1h = make_desc64(sb + 2u*A_TILE_B);
            uint64_t a1l = make_desc64(sb + 3u*A_TILE_B);
            uint64_t bh  = make_desc64(sb + 4u*A_TILE_B);
            uint64_t bl  = make_desc64(sb + 4u*A_TILE_B + B_TILE_B);
            #pragma unroll
            for (int ks = 0; ks < 2; ks++) {
                uint32_t acc = (it > 0 || ks > 0) ? 1u : 0u;
                uint64_t o = ks * 2;
                tc_mma_f16_ss(tmem,       a0h + o, bh + o, idesc, acc);
                tc_mma_f16_ss(tmem + 256, a1h + o, bh + o, idesc, acc);
                tc_mma_f16_ss(tmem,       a0h + o, bl + o, idesc, 1u);
                tc_mma_f16_ss(tmem + 256, a1h + o, bl + o, idesc, 1u);
                tc_mma_f16_ss(tmem,       a0l + o, bh + o, idesc, 1u);
                tc_mma_f16_ss(tmem + 256, a1l + o, bh + o, idesc, 1u);
            }
            tc_commit(empty_a[s]);
        }
        tc_commit(fin_a);
    }

    __syncthreads();
    mbar_wait(fin_a, 0);
    tc_fence_after();

    // epilogue: two M=128 halves; TMEM -> smem staging -> coalesced stores
    float* stg = (float*)smp;
    int w = tid >> 5, lane = tid & 31;
    #pragma unroll
    for (int half = 0; half < 2; half++) {
        if (w < 4) {
            for (int ch = 0; ch < 8; ch++) {
                uint32_t r[32];
                LDTM_X32(r, tmem + half * 256 + ch * 32);
                tc_wait_ld();
                #pragma unroll
                for (int j = 0; j < 32; j++)
                    stg[(size_t)(w * 32 + lane) * 260 + ch * 32 + j] = __uint_as_float(r[j]);
            }
        }
        __syncthreads();
        int c4 = (tid & 63) * 4;
        for (int rr = tid >> 6; rr < 128; rr += 4) {
            float4 v = *(float4*)&stg[(size_t)rr * 260 + c4];
            *(float4*)&C[(size_t)(m0 + half * 128 + rr) * N + n0 + c4] = v;
        }
        __syncthreads();
    }
    if (tid < 32) tc_dealloc(tmem, 512);
#else
    // ======== mma.sync bf16x3 fallback (bare sm_103; not selected on GB300) ========
    __nv_bfloat16* sAh = (__nv_bfloat16*)smp;
    __nv_bfloat16* sAl = sAh + 128 * 40;
    __nv_bfloat16* sBh = sAl + 128 * 40;
    __nv_bfloat16* sBl = sBh + 128 * 40;

    int lane = tid & 31, w = tid >> 5;
    int wm = w & 3, wn = w >> 2;

    for (int mh = 0; mh < 2; mh++)
    for (int nh = 0; nh < 2; nh++) {
        int m0h = m0 + mh * 128;
        int n0h = n0 + nh * 128;
        float acc[2][4][4];
        #pragma unroll
        for (int mi = 0; mi < 2; mi++)
            #pragma unroll
            for (int ni = 0; ni < 4; ni++)
                #pragma unroll
                for (int j = 0; j < 4; j++) acc[mi][ni][j] = 0.f;

        for (int k0 = 0; k0 < GK; k0 += 32) {
            __syncthreads();
            for (int cid = tid; cid < 512; cid += 256) {
                int r = cid >> 2, c = cid & 3;
                *(uint4*)&sAh[r*40 + c*8] = *(const uint4*)&Ah[(size_t)(m0h+r)*GK + k0 + c*8];
                *(uint4*)&sAl[r*40 + c*8] = *(const uint4*)&Al[(size_t)(m0h+r)*GK + k0 + c*8];
                *(uint4*)&sBh[r*40 + c*8] = *(const uint4*)&Bh[(size_t)(n0h+r)*GK + k0 + c*8];
                *(uint4*)&sBl[r*40 + c*8] = *(const uint4*)&Bl[(size_t)(n0h+r)*GK + k0 + c*8];
            }
            __syncthreads();
            #pragma unroll
            for (int ks = 0; ks < 2; ks++) {
                int kc = (lane & 3) * 2 + ks * 16;
                uint32_t ah[2][4], al[2][4];
                #pragma unroll
                for (int mi = 0; mi < 2; mi++) {
                    int r = wm * 32 + mi * 16 + (lane >> 2);
                    ah[mi][0] = *(uint32_t*)&sAh[r*40 + kc];
                    ah[mi][1] = *(uint32_t*)&sAh[(r+8)*40 + kc];
                    ah[mi][2] = *(uint32_t*)&sAh[r*40 + kc + 8];
                    ah[mi][3] = *(uint32_t*)&sAh[(r+8)*40 + kc + 8];
                    al[mi][0] = *(uint32_t*)&sAl[r*40 + kc];
                    al[mi][1] = *(uint32_t*)&sAl[(r+8)*40 + kc];
                    al[mi][2] = *(uint32_t*)&sAl[r*40 + kc + 8];
                    al[mi][3] = *(uint32_t*)&sAl[(r+8)*40 + kc + 8];
                }
                #pragma unroll
                for (int ni = 0; ni < 4; ni++) {
                    int nr = wn * 64 + ni * 8 + (lane >> 2);
                    uint32_t bh0 = *(uint32_t*)&sBh[nr*40 + kc];
                    uint32_t bh1 = *(uint32_t*)&sBh[nr*40 + kc + 8];
                    uint32_t bl0 = *(uint32_t*)&sBl[nr*40 + kc];
                    uint32_t bl1 = *(uint32_t*)&sBl[nr*40 + kc + 8];
                    #pragma unroll
                    for (int mi = 0; mi < 2; mi++) {
                        mma16816(acc[mi][ni], ah[mi], bh0, bh1);
                        mma16816(acc[mi][ni], ah[mi], bl0, bl1);
                        mma16816(acc[mi][ni], al[mi], bh0, bh1);
                    }
                }
            }
        }
        #pragma unroll
        for (int mi = 0; mi < 2; mi++)
            #pragma unroll
            for (int ni = 0; ni < 4; ni++) {
                int r = m0h + wm * 32 + mi * 16 + (lane >> 2);
                int c = n0h + wn * 64 + ni * 8 + (lane & 3) * 2;
                *(float2*)&C[(size_t)r * N + c] = make_float2(acc[mi][ni][0], acc[mi][ni][1]);
                *(float2*)&C[(size_t)(r+8) * N + c] = make_float2(acc[mi][ni][2], acc[mi][ni][3]);
            }
    }
#endif
}

// ---------------- attention (emits bf16 hi/lo output) ----------------
#define RT  16
#define KC  64
#define ATT_SMEM ((RT*HDIM + KC*(HDIM+1) + RT*LSEG + RT) * sizeof(float))

__global__ __launch_bounds__(128)
void attention_kernel() {
    extern __shared__ float sm[];
    float* Qs   = sm;
    float* Ks   = Qs + RT * HDIM;
    float* Ss   = Ks + KC * (HDIM + 1);
    float* rsum = Ss + RT * LSEG;

    int rt = blockIdx.x;
    int h  = blockIdx.y;
    int s  = blockIdx.z;
    int tid = threadIdx.x;
    int q_row0 = s * RQ + rt * RT;

    for (int i = tid; i < RT * HDIM; i += 128) {
        int r = i / HDIM, d = i % HDIM;
        Qs[r * HDIM + d] = g_q[(size_t)(q_row0 + r) * DIM + h * HDIM + d];
    }
    const float scale = rsqrtf((float)HDIM);
    int g = tid / KC;
    int l = tid % KC;
    __syncthreads();

    for (int lc = 0; lc < LSEG; lc += KC) {
        for (int i = tid; i < KC * (HDIM / 4); i += 128) {
            int kr = i / (HDIM / 4);
            int c4 = i % (HDIM / 4);
            float4 v = *reinterpret_cast<const float4*>(
                &g_kv[(size_t)(s * LSEG + lc + kr) * KVW + h * HDIM + c4 * 4]);
            float* dst = &Ks[kr * (HDIM + 1) + c4 * 4];
            dst[0] = v.x; dst[1] = v.y; dst[2] = v.z; dst[3] = v.w;
        }
        __syncthreads();
        float acc[8];
        #pragma unroll
        for (int r8 = 0; r8 < 8; r8++) acc[r8] = 0.f;
        #pragma unroll 4
        for (int d = 0; d < HDIM; d++) {
            float kv = Ks[l * (HDIM + 1) + d];
            #pragma unroll
            for (int r8 = 0; r8 < 8; r8++)
                acc[r8] += Qs[(g * 8 + r8) * HDIM + d] * kv;
        }
        #pragma unroll
        for (int r8 = 0; r8 < 8; r8++)
            Ss[(g * 8 + r8) * LSEG + lc + l] = acc[r8] * scale;
        __syncthreads();
    }

    int warp = tid / 32, lane = tid % 32;
    for (int r = warp; r < RT; r += 4) {
        float m = -1e30f;
        for (int i = lane; i < LSEG; i += 32) m = fmaxf(m, Ss[r * LSEG + i]);
        #pragma unroll
        for (int o = 16; o; o >>= 1) m = fmaxf(m, __shfl_xor_sync(0xffffffffu, m, o));
        float sum = 0.f;
        for (int i = lane; i < LSEG; i += 32) {
            float e = __expf(Ss[r * LSEG + i] - m);
            Ss[r * LSEG + i] = e;
            sum += e;
        }
        #pragma unroll
        for (int o = 16; o; o >>= 1) sum += __shfl_xor_sync(0xffffffffu, sum, o);
        if (lane == 0) rsum[r] = 1.0f / sum;
    }
    __syncthreads();

    int c = tid;
    float oacc[RT];
    #pragma unroll
    for (int r = 0; r < RT; r++) oacc[r] = 0.f;
    const float* vbase = &g_kv[(size_t)(s * LSEG) * KVW + NH * HDIM + h * HDIM + c];
    #pragma unroll 4
    for (int lk = 0; lk < LSEG; lk++) {
        float vv = vbase[(size_t)lk * KVW];
        #pragma unroll
        for (int r = 0; r < RT; r++) oacc[r] += Ss[r * LSEG + lk] * vv;
    }
    #pragma unroll
    for (int r = 0; r < RT; r++) {
        float val = oacc[r] * rsum[r];
        size_t o = (size_t)(q_row0 + r) * DIM + h * HDIM + c;
        __nv_bfloat16 hh = __float2bfloat16(val);
        g_o_hi[o] = hh;
        g_o_lo[o] = __float2bfloat16(val - __bfloat162float(hh));
    }
}

// ---------------- final: residual + rmsnorm ----------------
__global__ void final_kernel(const float* __restrict__ w, float* __restrict__ out) {
    int row = blockIdx.x;
    int tid = threadIdx.x;
    float vals[DIM / 256];
    float local = 0.f;
    #pragma unroll
    for (int i = 0; i < DIM / 256; i++) {
        int d = tid + i * 256;
        float v = g_tmp[(size_t)row * DIM + d] + g_queries[(size_t)row * DIM + d];
        vals[i] = v;
        local += v * v;
    }
    __shared__ float red[256];
    red[tid] = local; __syncthreads();
    for (int st = 128; st > 0; st >>= 1) {
        if (tid < st) red[tid] += red[tid + st];
        __syncthreads();
    }
    float rstd = rsqrtf(red[0] / DIM + EPS);
    #pragma unroll
    for (int i = 0; i < DIM / 256; i++) {
        int d = tid + i * 256;
        out[(size_t)row * DIM + d] = vals[i] * rstd * w[d];
    }
}

// ---------------- host: tensormap encode (driver entry point, no -lcuda) ----------------
typedef CUresult (*PFN_tmEncode)(CUtensorMap*, CUtensorMapDataType, cuuint32_t, void*,
                                 const cuuint64_t*, const cuuint64_t*, const cuuint32_t*,
                                 const cuuint32_t*, CUtensorMapInterleave, CUtensorMapSwizzle,
                                 CUtensorMapL2promotion, CUtensorMapFloatOOBfill);

static PFN_tmEncode get_encoder() {
    void* p = nullptr;
#if CUDART_VERSION >= 12050
    cudaDriverEntryPointQueryResult qr;
    cudaGetDriverEntryPointByVersion("cuTensorMapEncodeTiled", &p, 12000,
                                     cudaEnableDefault, &qr);
#else
    cudaGetDriverEntryPoint("cuTensorMapEncodeTiled", &p, cudaEnableDefault);
#endif
    return (PFN_tmEncode)p;
}

static void enc2d(PFN_tmEncode enc, CUtensorMap* m, void* base,
                  uint64_t rows, uint32_t boxRows) {
    cuuint64_t dims[2]    = {GK, rows};
    cuuint64_t strides[1] = {GK * 2};
    cuuint32_t box[2]     = {32, boxRows};
    cuuint32_t es[2]      = {1, 1};
    enc(m, CU_TENSOR_MAP_DATA_TYPE_BFLOAT16, 2, base, dims, strides, box, es,
        CU_TENSOR_MAP_INTERLEAVE_NONE, CU_TENSOR_MAP_SWIZZLE_64B,
        CU_TENSOR_MAP_L2_PROMOTION_L2_128B, CU_TENSOR_MAP_FLOAT_OOB_FILL_NONE);
}

// ---------------- launch ----------------
extern "C" void kernel_launch(void* const* d_in, const int* in_sizes, int n_in,
                              void* d_out, int out_size) {
    const float* x      = (const float*)d_in[0];
    const float* attn_w = (const float*)d_in[1];
    const float* wq     = (const float*)d_in[2];
    const float* wkv    = (const float*)d_in[3];
    const float* wo     = (const float*)d_in[4];
    const float* out_w  = (const float*)d_in[5];
    float* out = (float*)d_out;

    float *pq, *pkv, *ptmp;
    __nv_bfloat16 *pah, *pal, *pbkvh, *pbkvl, *pbqh, *pbql, *pboh, *pbol;
    __nv_bfloat16 *pqnh, *pqnl, *poh, *pol;
    cudaGetSymbolAddress((void**)&pq,    g_q);
    cudaGetSymbolAddress((void**)&pkv,   g_kv);
    cudaGetSymbolAddress((void**)&ptmp,  g_tmp);
    cudaGetSymbolAddress((void**)&pah,   g_a_hi);
    cudaGetSymbolAddress((void**)&pal,   g_a_lo);
    cudaGetSymbolAddress((void**)&pbkvh, g_bkv_hi);
    cudaGetSymbolAddress((void**)&pbkvl, g_bkv_lo);
    cudaGetSymbolAddress((void**)&pbqh,  g_bq_hi);
    cudaGetSymbolAddress((void**)&pbql,  g_bq_lo);
    cudaGetSymbolAddress((void**)&pboh,  g_bo_hi);
    cudaGetSymbolAddress((void**)&pbol,  g_bo_lo);
    cudaGetSymbolAddress((void**)&pqnh,  g_qn_hi);
    cudaGetSymbolAddress((void**)&pqnl,  g_qn_lo);
    cudaGetSymbolAddress((void**)&poh,   g_o_hi);
    cudaGetSymbolAddress((void**)&pol,   g_o_lo);

    // tensormaps
    PFN_tmEncode enc = get_encoder();
    CUtensorMap mQA_h, mQA_l, mQB_h, mQB_l;     // q gemm
    CUtensorMap mKA_h, mKA_l, mKB_h, mKB_l;     // kv gemm
    CUtensorMap mOA_h, mOA_l, mOB_h, mOB_l;     // o gemm
    enc2d(enc, &mQA_h, pqnh,  NQ,   128);  enc2d(enc, &mQA_l, pqnl,  NQ,   128);
    enc2d(enc, &mQB_h, pbqh,  DIM,  256);  enc2d(enc, &mQB_l, pbql,  DIM,  256);
    enc2d(enc, &mKA_h, pah,   NTOK, 128);  enc2d(enc, &mKA_l, pal,   NTOK, 128);
    enc2d(enc, &mKB_h, pbkvh, KVW,  256);  enc2d(enc, &mKB_l, pbkvl, KVW,  256);
    enc2d(enc, &mOA_h, poh,   NQ,   128);  enc2d(enc, &mOA_l, pol,   NQ,   128);
    enc2d(enc, &mOB_h, pboh,  DIM,  256);  enc2d(enc, &mOB_l, pbol,  DIM,  256);

    cudaFuncSetAttribute(attention_kernel,
                         cudaFuncAttributeMaxDynamicSharedMemorySize, (int)ATT_SMEM);
    cudaFuncSetAttribute(gemm3_kernel,
                         cudaFuncAttributeMaxDynamicSharedMemorySize, (int)GEMM_SMEM);

    // weight prep (transpose + hi/lo split)
    tsplit_kernel<<<dim3(KVW/32, DIM/32), dim3(32,8)>>>(wkv, pbkvh, pbkvl, DIM, KVW);
    tsplit_kernel<<<dim3(DIM/32, DIM/32), dim3(32,8)>>>(wq, pbqh, pbql, DIM, DIM);
    tsplit_kernel<<<dim3(DIM/32, DIM/32), dim3(32,8)>>>(wo, pboh, pbol, DIM, DIM);

    // fused x-split + pooling + attention rmsnorm
    pool_rmsnorm_kernel<<<NQ, 256>>>(x, attn_w);

    // q = qn @ wq : M=2048, N=4096
    gemm3_kernel<<<(NQ/BM)*(DIM/BN), 256, GEMM_SMEM>>>(DIM, NQ/BM, DIM/BN,
        mQA_h, mQA_l, mQB_h, mQB_l, pqnh, pqnl, pbqh, pbql, pq);
    // kv = x @ wkv : M=16384, N=8192
    gemm3_kernel<<<(NTOK/BM)*(KVW/BN), 256, GEMM_SMEM>>>(KVW, NTOK/BM, KVW/BN,
        mKA_h, mKA_l, mKB_h, mKB_l, pah, pal, pbkvh, pbkvl, pkv);
    // attention
    attention_kernel<<<dim3(RQ / RT, NH, SEGN), 128, ATT_SMEM>>>();
    // tmp = o @ wo : M=2048, N=4096
    gemm3_kernel<<<(NQ/BM)*(DIM/BN), 256, GEMM_SMEM>>>(DIM, NQ/BM, DIM/BN,
        mOA_h, mOA_l, mOB_h, mOB_l, poh, pol, pboh, pbol, ptmp);
    // residual + rmsnorm
    final_kernel<<<NQ, 256>>>(out_w, out);
}

// round 6
// speedup vs baseline: 10.8478x; 1.3400x over previous
#include <cuda_runtime.h>
#include <cuda.h>
#include <cuda_bf16.h>
#include <math.h>
#include <stdint.h>

// ---------------- problem constants ----------------
#define SEGN   32
#define LSEG   512
#define RQ     64
#define POOLN  8
#define NH     32
#define HDIM   128
#define DIM    4096
#define NQ     (SEGN*RQ)     // 2048
#define NTOK   (SEGN*LSEG)   // 16384
#define KVW    (2*NH*HDIM)   // 8192
#define EPS    1e-5f

#if defined(__CUDA_ARCH_FEAT_SM103_ALL) || defined(__CUDA_ARCH_FEAT_SM100_ALL)
#define TC_OK 1
#else
#define TC_OK 0
#endif

// ---------------- scratch ----------------
__device__ __align__(128) float g_queries[(size_t)NQ*DIM];
__device__ __align__(128) float g_q[(size_t)NQ*DIM];
__device__ __align__(128) float g_kv[(size_t)NTOK*KVW];
__device__ __align__(128) float g_tmp[(size_t)NQ*DIM];

__device__ __align__(128) __nv_bfloat16 g_a_hi[(size_t)NTOK*DIM];
__device__ __align__(128) __nv_bfloat16 g_a_lo[(size_t)NTOK*DIM];
__device__ __align__(128) __nv_bfloat16 g_bkv_hi[(size_t)KVW*DIM];
__device__ __align__(128) __nv_bfloat16 g_bkv_lo[(size_t)KVW*DIM];
__device__ __align__(128) __nv_bfloat16 g_bq_hi[(size_t)DIM*DIM];
__device__ __align__(128) __nv_bfloat16 g_bq_lo[(size_t)DIM*DIM];
__device__ __align__(128) __nv_bfloat16 g_bo_hi[(size_t)DIM*DIM];
__device__ __align__(128) __nv_bfloat16 g_bo_lo[(size_t)DIM*DIM];
__device__ __align__(128) __nv_bfloat16 g_qn_hi[(size_t)NQ*DIM];
__device__ __align__(128) __nv_bfloat16 g_qn_lo[(size_t)NQ*DIM];
__device__ __align__(128) __nv_bfloat16 g_o_hi[(size_t)NQ*DIM];
__device__ __align__(128) __nv_bfloat16 g_o_lo[(size_t)NQ*DIM];

// ---------------- generic helpers ----------------
__device__ __forceinline__ uint32_t s2u(const void* p) {
    return (uint32_t)__cvta_generic_to_shared(p);
}
__device__ __forceinline__ void mbar_init(uint32_t a, uint32_t cnt) {
    asm volatile("mbarrier.init.shared.b64 [%0], %1;" :: "r"(a), "r"(cnt) : "memory");
}
__device__ __forceinline__ void mbar_wait(uint32_t a, uint32_t phase) {
    uint32_t done;
    do {
        asm volatile("{\n\t.reg .pred p;\n\t"
                     "mbarrier.try_wait.parity.shared::cta.b64 p, [%1], %2, 0x989680;\n\t"
                     "selp.b32 %0, 1, 0, p;\n\t}"
                     : "=r"(done) : "r"(a), "r"(phase) : "memory");
    } while (!done);
}
__device__ __forceinline__ void mbar_expect_tx(uint32_t a, uint32_t bytes) {
    asm volatile("mbarrier.arrive.expect_tx.shared.b64 _, [%0], %1;"
                 :: "r"(a), "r"(bytes) : "memory");
}
__device__ __forceinline__ void tma_load_2d(uint32_t dst, const void* map,
                                            int cx, int cy, uint32_t bar) {
    asm volatile("cp.async.bulk.tensor.2d.shared::cta.global.tile.mbarrier::complete_tx::bytes "
                 "[%0], [%1, {%2, %3}], [%4];"
                 :: "r"(dst), "l"(map), "r"(cx), "r"(cy), "r"(bar) : "memory");
}
// bf16 mma (portable)
__device__ __forceinline__ void mma16816(float* c, const uint32_t* a, uint32_t b0, uint32_t b1) {
    asm volatile("mma.sync.aligned.m16n8k16.row.col.f32.bf16.bf16.f32 "
                 "{%0,%1,%2,%3}, {%4,%5,%6,%7}, {%8,%9}, {%0,%1,%2,%3};"
                 : "+f"(c[0]), "+f"(c[1]), "+f"(c[2]), "+f"(c[3])
                 : "r"(a[0]), "r"(a[1]), "r"(a[2]), "r"(a[3]), "r"(b0), "r"(b1));
}
// split float2 -> packed bf16x2 hi + lo
__device__ __forceinline__ void split2(float2 v, uint32_t& hi, uint32_t& lo) {
    __nv_bfloat16 hx = __float2bfloat16(v.x), hy = __float2bfloat16(v.y);
    __nv_bfloat162 hp = __halves2bfloat162(hx, hy);
    hi = *(uint32_t*)&hp;
    __nv_bfloat162 lp = __halves2bfloat162(
        __float2bfloat16(v.x - __bfloat162float(hx)),
        __float2bfloat16(v.y - __bfloat162float(hy)));
    lo = *(uint32_t*)&lp;
}

#if TC_OK
// ---------------- tcgen05 helpers ('a' targets only) ----------------
__device__ __forceinline__ void tc_alloc(uint32_t smem_dst, uint32_t ncols) {
    asm volatile("tcgen05.alloc.cta_group::1.sync.aligned.shared::cta.b32 [%0], %1;"
                 :: "r"(smem_dst), "r"(ncols) : "memory");
}
__device__ __forceinline__ void tc_dealloc(uint32_t tmem, uint32_t ncols) {
    asm volatile("tcgen05.relinquish_alloc_permit.cta_group::1.sync.aligned;");
    asm volatile("tcgen05.dealloc.cta_group::1.sync.aligned.b32 %0, %1;" :: "r"(tmem), "r"(ncols));
}
__device__ __forceinline__ void tc_commit(uint32_t bar) {
    asm volatile("tcgen05.commit.cta_group::1.mbarrier::arrive::one.shared::cluster.b64 [%0];"
                 :: "r"(bar) : "memory");
}
__device__ __forceinline__ void tc_mma_f16_ss(uint32_t d, uint64_t ad, uint64_t bd,
                                              uint32_t idesc, uint32_t accum) {
    asm volatile("{\n\t.reg .pred p;\n\t"
                 "setp.ne.u32 p, %4, 0;\n\t"
                 "tcgen05.mma.cta_group::1.kind::f16 [%0], %1, %2, %3, {%5, %5, %5, %5}, p;\n\t}"
                 :: "r"(d), "l"(ad), "l"(bd), "r"(idesc), "r"(accum), "r"(0u) : "memory");
}
__device__ __forceinline__ void tc_fence_after() {
    asm volatile("tcgen05.fence::after_thread_sync;" ::: "memory");
}
#define LDTM_X32(r, addr) \
    asm volatile("tcgen05.ld.sync.aligned.32x32b.x32.b32 " \
        "{%0, %1, %2, %3, %4, %5, %6, %7, %8, %9, %10, %11, %12, %13, %14, %15, " \
        "%16, %17, %18, %19, %20, %21, %22, %23, %24, %25, %26, %27, %28, %29, %30, %31}, [%32];" \
        : "=r"((r)[0]), "=r"((r)[1]), "=r"((r)[2]), "=r"((r)[3]), \
          "=r"((r)[4]), "=r"((r)[5]), "=r"((r)[6]), "=r"((r)[7]), \
          "=r"((r)[8]), "=r"((r)[9]), "=r"((r)[10]), "=r"((r)[11]), \
          "=r"((r)[12]), "=r"((r)[13]), "=r"((r)[14]), "=r"((r)[15]), \
          "=r"((r)[16]), "=r"((r)[17]), "=r"((r)[18]), "=r"((r)[19]), \
          "=r"((r)[20]), "=r"((r)[21]), "=r"((r)[22]), "=r"((r)[23]), \
          "=r"((r)[24]), "=r"((r)[25]), "=r"((r)[26]), "=r"((r)[27]), \
          "=r"((r)[28]), "=r"((r)[29]), "=r"((r)[30]), "=r"((r)[31]) \
        : "r"(addr))
__device__ __forceinline__ void tc_wait_ld() {
    asm volatile("tcgen05.wait::ld.sync.aligned;" ::: "memory");
}
static __device__ __forceinline__ uint64_t make_desc64(uint32_t addr) {
    const uint64_t base = (uint64_t(4) << 61) | (uint64_t(1) << 46) |
                          (uint64_t(32) << 32) | (uint64_t(1) << 16);
    return base | ((uint64_t)(addr >> 4) & 0x3FFFull);
}
#endif

// ---------------- transpose-split ----------------
__global__ void tsplit_kernel(const float* __restrict__ in,
                              __nv_bfloat16* __restrict__ hi,
                              __nv_bfloat16* __restrict__ lo,
                              int Kdim, int Ndim) {
    __shared__ float t[32][33];
    int n0 = blockIdx.x * 32, k0 = blockIdx.y * 32;
    int tx = threadIdx.x, ty = threadIdx.y;
    for (int r = ty; r < 32; r += 8)
        t[r][tx] = in[(size_t)(k0 + r) * Ndim + n0 + tx];
    __syncthreads();
    for (int r = ty; r < 32; r += 8) {
        float a = t[tx][r];
        size_t o = (size_t)(n0 + r) * Kdim + k0 + tx;
        __nv_bfloat16 h = __float2bfloat16(a);
        hi[o] = h;
        lo[o] = __float2bfloat16(a - __bfloat162float(h));
    }
}

// ---------------- fused: x split + pooling + attention rmsnorm ----------------
__global__ void pool_rmsnorm_kernel(const float* __restrict__ x,
                                    const float* __restrict__ w) {
    int row = blockIdx.x;
    int tid = threadIdx.x;
    const float* base = x + (size_t)row * POOLN * DIM;
    float local = 0.f;
    for (int d = tid; d < DIM; d += 256) {
        float s = 0.f;
        #pragma unroll
        for (int p = 0; p < POOLN; p++) {
            float v = base[(size_t)p*DIM + d];
            __nv_bfloat16 h = __float2bfloat16(v);
            size_t o = (size_t)(row * POOLN + p) * DIM + d;
            g_a_hi[o] = h;
            g_a_lo[o] = __float2bfloat16(v - __bfloat162float(h));
            s += v;
        }
        s *= (1.0f / POOLN);
        g_queries[(size_t)row*DIM + d] = s;
        local += s * s;
    }
    __shared__ float red[256];
    red[tid] = local; __syncthreads();
    for (int st = 128; st > 0; st >>= 1) {
        if (tid < st) red[tid] += red[tid + st];
        __syncthreads();
    }
    float rstd = rsqrtf(red[0] / DIM + EPS);
    for (int d = tid; d < DIM; d += 256) {
        float v = g_queries[(size_t)row*DIM + d] * rstd * w[d];
        __nv_bfloat16 h = __float2bfloat16(v);
        g_qn_hi[(size_t)row*DIM + d] = h;
        g_qn_lo[(size_t)row*DIM + d] = __float2bfloat16(v - __bfloat162float(h));
    }
}

// ---------------- bf16x3 GEMM (tcgen05 + TMA), unchanged from R5 ----------------
#define BM 256
#define BN 256
#define GK 4096
#define KITERS (GK/32)
#define A_TILE_B 8192u
#define B_TILE_B 16384u
#define STAGE_BYTES (4u*A_TILE_B + 2u*B_TILE_B)
#define NSTAGE 3
#define GEMM_SMEM (NSTAGE*STAGE_BYTES + 1024)

__global__ __launch_bounds__(256, 1)
void gemm3_kernel(int N, int nbm, int nbn,
                  const __grid_constant__ CUtensorMap mAh,
                  const __grid_constant__ CUtensorMap mAl,
                  const __grid_constant__ CUtensorMap mBh,
                  const __grid_constant__ CUtensorMap mBl,
                  const __nv_bfloat16* __restrict__ Ah,
                  const __nv_bfloat16* __restrict__ Al,
                  const __nv_bfloat16* __restrict__ Bh,
                  const __nv_bfloat16* __restrict__ Bl,
                  float* __restrict__ C) {
    extern __shared__ char smraw[];
    char* smp = (char*)((((uintptr_t)smraw) + 1023) & ~(uintptr_t)1023);
    int tid = threadIdx.x;

    const int GM = 16;
    int bid = blockIdx.x;
    int group = bid / (GM * nbn);
    int first_m = group * GM;
    int gsz = min(nbm - first_m, GM);
    int pm = first_m + (bid % gsz);
    int pn = (bid % (GM * nbn)) / gsz;
    int m0 = pm * BM, n0 = pn * BN;

#if TC_OK
    uint32_t sb0 = s2u(smp);
    __shared__ __align__(8) unsigned long long full_b[NSTAGE], empty_b[NSTAGE], fin_b;
    __shared__ uint32_t tmem_ptr_sh;

    uint32_t full_a[NSTAGE], empty_a[NSTAGE], fin_a;
    #pragma unroll
    for (int i = 0; i < NSTAGE; i++) {
        full_a[i] = s2u(&full_b[i]);
        empty_a[i] = s2u(&empty_b[i]);
    }
    fin_a = s2u(&fin_b);

    if (tid < 32) tc_alloc(s2u(&tmem_ptr_sh), 512);
    if (tid == 0) {
        #pragma unroll
        for (int i = 0; i < NSTAGE; i++) {
            mbar_init(full_a[i], 1);
            mbar_init(empty_a[i], 1);
        }
        mbar_init(fin_a, 1);
    }
    __syncthreads();
    uint32_t tmem = tmem_ptr_sh;

    const uint32_t idesc = (1u<<4) | (1u<<7) | (1u<<10) | ((BN/8)<<17) | (8u<<24);

    if (tid == 32) {
        for (int it = 0; it < KITERS; it++) {
            int s = it % NSTAGE;
            uint32_t ph = ((it / NSTAGE) & 1) ^ 1u;
            mbar_wait(empty_a[s], ph);
            int k0 = it * 32;
            uint32_t sb = sb0 + s * STAGE_BYTES;
            uint32_t bar = full_a[s];
            mbar_expect_tx(bar, STAGE_BYTES);
            tma_load_2d(sb,                          &mAh, k0, m0,       bar);
            tma_load_2d(sb + A_TILE_B,               &mAl, k0, m0,       bar);
            tma_load_2d(sb + 2u*A_TILE_B,            &mAh, k0, m0 + 128, bar);
            tma_load_2d(sb + 3u*A_TILE_B,            &mAl, k0, m0 + 128, bar);
            tma_load_2d(sb + 4u*A_TILE_B,            &mBh, k0, n0,       bar);
            tma_load_2d(sb + 4u*A_TILE_B + B_TILE_B, &mBl, k0, n0,       bar);
        }
    } else if (tid == 0) {
        for (int it = 0; it < KITERS; it++) {
            int s = it % NSTAGE;
            uint32_t ph = (it / NSTAGE) & 1;
            mbar_wait(full_a[s], ph);
            uint32_t sb = sb0 + s * STAGE_BYTES;
            uint64_t a0h = make_desc64(sb);
            uint64_t a0l = make_desc64(sb + A_TILE_B);
            uint64_t a1h = make_desc64(sb + 2u*A_TILE_B);
            uint64_t a1l = make_desc64(sb + 3u*A_TILE_B);
            uint64_t bh  = make_desc64(sb + 4u*A_TILE_B);
            uint64_t bl  = make_desc64(sb + 4u*A_TILE_B + B_TILE_B);
            #pragma unroll
            for (int ks = 0; ks < 2; ks++) {
                uint32_t acc = (it > 0 || ks > 0) ? 1u : 0u;
                uint64_t o = ks * 2;
                tc_mma_f16_ss(tmem,       a0h + o, bh + o, idesc, acc);
                tc_mma_f16_ss(tmem + 256, a1h + o, bh + o, idesc, acc);
                tc_mma_f16_ss(tmem,       a0h + o, bl + o, idesc, 1u);
                tc_mma_f16_ss(tmem + 256, a1h + o, bl + o, idesc, 1u);
                tc_mma_f16_ss(tmem,       a0l + o, bh + o, idesc, 1u);
                tc_mma_f16_ss(tmem + 256, a1l + o, bh + o, idesc, 1u);
            }
            tc_commit(empty_a[s]);
        }
        tc_commit(fin_a);
    }

    __syncthreads();
    mbar_wait(fin_a, 0);
    tc_fence_after();

    float* stg = (float*)smp;
    int w = tid >> 5, lane = tid & 31;
    #pragma unroll
    for (int half = 0; half < 2; half++) {
        if (w < 4) {
            for (int ch = 0; ch < 8; ch++) {
                uint32_t r[32];
                LDTM_X32(r, tmem + half * 256 + ch * 32);
                tc_wait_ld();
                #pragma unroll
                for (int j = 0; j < 32; j++)
                    stg[(size_t)(w * 32 + lane) * 260 + ch * 32 + j] = __uint_as_float(r[j]);
            }
        }
        __syncthreads();
        int c4 = (tid & 63) * 4;
        for (int rr = tid >> 6; rr < 128; rr += 4) {
            float4 v = *(float4*)&stg[(size_t)rr * 260 + c4];
            *(float4*)&C[(size_t)(m0 + half * 128 + rr) * N + n0 + c4] = v;
        }
        __syncthreads();
    }
    if (tid < 32) tc_dealloc(tmem, 512);
#else
    // mma.sync fallback (bare sm_103; not selected on GB300)
    __nv_bfloat16* sAh = (__nv_bfloat16*)smp;
    __nv_bfloat16* sAl = sAh + 128 * 40;
    __nv_bfloat16* sBh = sAl + 128 * 40;
    __nv_bfloat16* sBl = sBh + 128 * 40;

    int lane = tid & 31, w = tid >> 5;
    int wm = w & 3, wn = w >> 2;

    for (int mh = 0; mh < 2; mh++)
    for (int nh = 0; nh < 2; nh++) {
        int m0h = m0 + mh * 128;
        int n0h = n0 + nh * 128;
        float acc[2][4][4];
        #pragma unroll
        for (int mi = 0; mi < 2; mi++)
            #pragma unroll
            for (int ni = 0; ni < 4; ni++)
                #pragma unroll
                for (int j = 0; j < 4; j++) acc[mi][ni][j] = 0.f;

        for (int k0 = 0; k0 < GK; k0 += 32) {
            __syncthreads();
            for (int cid = tid; cid < 512; cid += 256) {
                int r = cid >> 2, c = cid & 3;
                *(uint4*)&sAh[r*40 + c*8] = *(const uint4*)&Ah[(size_t)(m0h+r)*GK + k0 + c*8];
                *(uint4*)&sAl[r*40 + c*8] = *(const uint4*)&Al[(size_t)(m0h+r)*GK + k0 + c*8];
                *(uint4*)&sBh[r*40 + c*8] = *(const uint4*)&Bh[(size_t)(n0h+r)*GK + k0 + c*8];
                *(uint4*)&sBl[r*40 + c*8] = *(const uint4*)&Bl[(size_t)(n0h+r)*GK + k0 + c*8];
            }
            __syncthreads();
            #pragma unroll
            for (int ks = 0; ks < 2; ks++) {
                int kc = (lane & 3) * 2 + ks * 16;
                uint32_t ah[2][4], al[2][4];
                #pragma unroll
                for (int mi = 0; mi < 2; mi++) {
                    int r = wm * 32 + mi * 16 + (lane >> 2);
                    ah[mi][0] = *(uint32_t*)&sAh[r*40 + kc];
                    ah[mi][1] = *(uint32_t*)&sAh[(r+8)*40 + kc];
                    ah[mi][2] = *(uint32_t*)&sAh[r*40 + kc + 8];
                    ah[mi][3] = *(uint32_t*)&sAh[(r+8)*40 + kc + 8];
                    al[mi][0] = *(uint32_t*)&sAl[r*40 + kc];
                    al[mi][1] = *(uint32_t*)&sAl[(r+8)*40 + kc];
                    al[mi][2] = *(uint32_t*)&sAl[r*40 + kc + 8];
                    al[mi][3] = *(uint32_t*)&sAl[(r+8)*40 + kc + 8];
                }
                #pragma unroll
                for (int ni = 0; ni < 4; ni++) {
                    int nr = wn * 64 + ni * 8 + (lane >> 2);
                    uint32_t bh0 = *(uint32_t*)&sBh[nr*40 + kc];
                    uint32_t bh1 = *(uint32_t*)&sBh[nr*40 + kc + 8];
                    uint32_t bl0 = *(uint32_t*)&sBl[nr*40 + kc];
                    uint32_t bl1 = *(uint32_t*)&sBl[nr*40 + kc + 8];
                    #pragma unroll
                    for (int mi = 0; mi < 2; mi++) {
                        mma16816(acc[mi][ni], ah[mi], bh0, bh1);
                        mma16816(acc[mi][ni], ah[mi], bl0, bl1);
                        mma16816(acc[mi][ni], al[mi], bh0, bh1);
                    }
                }
            }
        }
        #pragma unroll
        for (int mi = 0; mi < 2; mi++)
            #pragma unroll
            for (int ni = 0; ni < 4; ni++) {
                int r = m0h + wm * 32 + mi * 16 + (lane >> 2);
                int c = n0h + wn * 64 + ni * 8 + (lane & 3) * 2;
                *(float2*)&C[(size_t)r * N + c] = make_float2(acc[mi][ni][0], acc[mi][ni][1]);
                *(float2*)&C[(size_t)(r+8) * N + c] = make_float2(acc[mi][ni][2], acc[mi][ni][3]);
            }
    }
#endif
}

// ---------------- tensor-core attention: one (seg, head) per CTA ----------------
// smem layout (bytes):
//   sS   : 64 x 514 fp32           = 131584   (scores / unnormalized probs)
//   sQh  : 64 rows x 132 bf16      =  16896
//   sQl  : 64 rows x 132 bf16      =  16896
//   sKVh : K chunk 64x132 bf16 / Vt 128x66 bf16 = 16896
//   sKVl : same                    =  16896
//   rinv : 64 fp32                 =    256
#define SROW 514
#define QROW 132
#define VTROW 66
#define OFF_QH 131584
#define OFF_QL (OFF_QH + 16896)
#define OFF_KH (OFF_QL + 16896)
#define OFF_KL (OFF_KH + 16896)
#define OFF_RI (OFF_KL + 16896)
#define ATT2_SMEM (OFF_RI + 256)

__global__ __launch_bounds__(256, 1)
void attention2_kernel() {
    extern __shared__ char asmem[];
    float* sS = (float*)asmem;
    __nv_bfloat16* sQh = (__nv_bfloat16*)(asmem + OFF_QH);
    __nv_bfloat16* sQl = (__nv_bfloat16*)(asmem + OFF_QL);
    __nv_bfloat16* sKh = (__nv_bfloat16*)(asmem + OFF_KH);   // also sVth
    __nv_bfloat16* sKl = (__nv_bfloat16*)(asmem + OFF_KL);   // also sVtl
    float* rinv = (float*)(asmem + OFF_RI);

    int tid = threadIdx.x;
    int h = blockIdx.x & 31;
    int s = blockIdx.x >> 5;
    int q0 = s * RQ;
    int t0 = s * LSEG;

    int w = tid >> 5, lane = tid & 31;
    int wm = w & 3, wn = w >> 2;     // wm: 4 m-tiles of 16; wn: 2 halves
    int lr = lane >> 2, lc = lane & 3;

    // load Q (64 x 128) -> bf16 hi/lo smem
    for (int i = tid; i < 64 * 64; i += 256) {
        int r = i >> 6, c2 = (i & 63) * 2;
        float2 v = *(float2*)&g_q[(size_t)(q0 + r) * DIM + h * HDIM + c2];
        uint32_t hi, lo; split2(v, hi, lo);
        *(uint32_t*)&sQh[r * QROW + c2] = hi;
        *(uint32_t*)&sQl[r * QROW + c2] = lo;
    }

    const float scale = rsqrtf((float)HDIM);

    // ---- phase 1: S = scale * Q K^T ----
    for (int ck = 0; ck < 8; ck++) {
        __syncthreads();
        for (int i = tid; i < 64 * 64; i += 256) {
            int r = i >> 6, c2 = (i & 63) * 2;
            float2 v = *(float2*)&g_kv[(size_t)(t0 + ck * 64 + r) * KVW + h * HDIM + c2];
            uint32_t hi, lo; split2(v, hi, lo);
            *(uint32_t*)&sKh[r * QROW + c2] = hi;
            *(uint32_t*)&sKl[r * QROW + c2] = lo;
        }
        __syncthreads();

        float acc[4][4];
        #pragma unroll
        for (int nt = 0; nt < 4; nt++)
            #pragma unroll
            for (int j = 0; j < 4; j++) acc[nt][j] = 0.f;

        #pragma unroll
        for (int kk = 0; kk < 8; kk++) {
            int k0 = kk * 16;
            int r0 = wm * 16 + lr;
            uint32_t ah[4], al[4];
            ah[0] = *(uint32_t*)&sQh[r0 * QROW + k0 + lc * 2];
            ah[1] = *(uint32_t*)&sQh[(r0 + 8) * QROW + k0 + lc * 2];
            ah[2] = *(uint32_t*)&sQh[r0 * QROW + k0 + 8 + lc * 2];
            ah[3] = *(uint32_t*)&sQh[(r0 + 8) * QROW + k0 + 8 + lc * 2];
            al[0] = *(uint32_t*)&sQl[r0 * QROW + k0 + lc * 2];
            al[1] = *(uint32_t*)&sQl[(r0 + 8) * QROW + k0 + lc * 2];
            al[2] = *(uint32_t*)&sQl[r0 * QROW + k0 + 8 + lc * 2];
            al[3] = *(uint32_t*)&sQl[(r0 + 8) * QROW + k0 + 8 + lc * 2];
            #pragma unroll
            for (int nt = 0; nt < 4; nt++) {
                int nb = (wn * 4 + nt) * 8;
                uint32_t bh0 = *(uint32_t*)&sKh[(nb + lr) * QROW + k0 + lc * 2];
                uint32_t bh1 = *(uint32_t*)&sKh[(nb + lr) * QROW + k0 + 8 + lc * 2];
                uint32_t bl0 = *(uint32_t*)&sKl[(nb + lr) * QROW + k0 + lc * 2];
                uint32_t bl1 = *(uint32_t*)&sKl[(nb + lr) * QROW + k0 + 8 + lc * 2];
                mma16816(acc[nt], ah, bh0, bh1);
                mma16816(acc[nt], ah, bl0, bl1);
                mma16816(acc[nt], al, bh0, bh1);
            }
        }
        int row = wm * 16 + lr;
        #pragma unroll
        for (int nt = 0; nt < 4; nt++) {
            int col = ck * 64 + (wn * 4 + nt) * 8 + lc * 2;
            *(float2*)&sS[row * SROW + col] =
                make_float2(acc[nt][0] * scale, acc[nt][1] * scale);
            *(float2*)&sS[(row + 8) * SROW + col] =
                make_float2(acc[nt][2] * scale, acc[nt][3] * scale);
        }
    }
    __syncthreads();

    // ---- phase 2: softmax (store unnormalized e; rinv per row) ----
    for (int j = 0; j < 8; j++) {
        int r = w * 8 + j;
        float m = -1e30f;
        for (int i = lane; i < LSEG; i += 32) m = fmaxf(m, sS[r * SROW + i]);
        #pragma unroll
        for (int o = 16; o; o >>= 1) m = fmaxf(m, __shfl_xor_sync(0xffffffffu, m, o));
        float sum = 0.f;
        for (int i = lane; i < LSEG; i += 32) {
            float e = __expf(sS[r * SROW + i] - m);
            sS[r * SROW + i] = e;
            sum += e;
        }
        #pragma unroll
        for (int o = 16; o; o >>= 1) sum += __shfl_xor_sync(0xffffffffu, sum, o);
        if (lane == 0) rinv[r] = 1.0f / sum;
    }

    // ---- phase 3: O = P V (warp: m-tile wm, hd half wn) ----
    float oacc[8][4];
    #pragma unroll
    for (int nt = 0; nt < 8; nt++)
        #pragma unroll
        for (int j = 0; j < 4; j++) oacc[nt][j] = 0.f;

    for (int ck = 0; ck < 8; ck++) {
        __syncthreads();
        // load V chunk transposed: sVt[hd][t], rows padded to 66 halfwords
        for (int i = tid; i < 64 * 64; i += 256) {
            int t = i >> 6, hd2 = (i & 63) * 2;
            float2 v = *(float2*)&g_kv[(size_t)(t0 + ck * 64 + t) * KVW
                                       + NH * HDIM + h * HDIM + hd2];
            __nv_bfloat16 hx = __float2bfloat16(v.x), hy = __float2bfloat16(v.y);
            sKh[hd2 * VTROW + t] = hx;
            sKh[(hd2 + 1) * VTROW + t] = hy;
            sKl[hd2 * VTROW + t] = __float2bfloat16(v.x - __bfloat162float(hx));
            sKl[(hd2 + 1) * VTROW + t] = __float2bfloat16(v.y - __bfloat162float(hy));
        }
        __syncthreads();

        #pragma unroll
        for (int kk = 0; kk < 4; kk++) {
            int kt = ck * 64 + kk * 16;       // global token col in sS
            int kl = kk * 16;                 // chunk-local token in sVt
            int r0 = wm * 16 + lr;
            float2 p0 = *(float2*)&sS[r0 * SROW + kt + lc * 2];
            float2 p1 = *(float2*)&sS[(r0 + 8) * SROW + kt + lc * 2];
            float2 p2 = *(float2*)&sS[r0 * SROW + kt + 8 + lc * 2];
            float2 p3 = *(float2*)&sS[(r0 + 8) * SROW + kt + 8 + lc * 2];
            uint32_t ah[4], al[4];
            split2(p0, ah[0], al[0]);
            split2(p1, ah[1], al[1]);
            split2(p2, ah[2], al[2]);
            split2(p3, ah[3], al[3]);
            #pragma unroll
            for (int nt = 0; nt < 8; nt++) {
                int hd0 = wn * 64 + nt * 8;
                uint32_t bh0 = *(uint32_t*)&sKh[(hd0 + lr) * VTROW + kl + lc * 2];
                uint32_t bh1 = *(uint32_t*)&sKh[(hd0 + lr) * VTROW + kl + 8 + lc * 2];
                uint32_t bl0 = *(uint32_t*)&sKl[(hd0 + lr) * VTROW + kl + lc * 2];
                uint32_t bl1 = *(uint32_t*)&sKl[(hd0 + lr) * VTROW + kl + 8 + lc * 2];
                mma16816(oacc[nt], ah, bh0, bh1);
                mma16816(oacc[nt], al, bh0, bh1);
                mma16816(oacc[nt], ah, bl0, bl1);
            }
        }
    }

    // ---- writeback: normalize, split to bf16 hi/lo for the o-projection ----
    {
        int r0 = wm * 16 + lr;
        float ri0 = rinv[r0], ri1 = rinv[r0 + 8];
        #pragma unroll
        for (int nt = 0; nt < 8; nt++) {
            int c0 = h * HDIM + wn * 64 + nt * 8 + lc * 2;
            uint32_t hi, lo;
            split2(make_float2(oacc[nt][0] * ri0, oacc[nt][1] * ri0), hi, lo);
            *(uint32_t*)&g_o_hi[(size_t)(q0 + r0) * DIM + c0] = hi;
            *(uint32_t*)&g_o_lo[(size_t)(q0 + r0) * DIM + c0] = lo;
            split2(make_float2(oacc[nt][2] * ri1, oacc[nt][3] * ri1), hi, lo);
            *(uint32_t*)&g_o_hi[(size_t)(q0 + r0 + 8) * DIM + c0] = hi;
            *(uint32_t*)&g_o_lo[(size_t)(q0 + r0 + 8) * DIM + c0] = lo;
        }
    }
}

// ---------------- final: residual + rmsnorm ----------------
__global__ void final_kernel(const float* __restrict__ w, float* __restrict__ out) {
    int row = blockIdx.x;
    int tid = threadIdx.x;
    float vals[DIM / 256];
    float local = 0.f;
    #pragma unroll
    for (int i = 0; i < DIM / 256; i++) {
        int d = tid + i * 256;
        float v = g_tmp[(size_t)row * DIM + d] + g_queries[(size_t)row * DIM + d];
        vals[i] = v;
        local += v * v;
    }
    __shared__ float red[256];
    red[tid] = local; __syncthreads();
    for (int st = 128; st > 0; st >>= 1) {
        if (tid < st) red[tid] += red[tid + st];
        __syncthreads();
    }
    float rstd = rsqrtf(red[0] / DIM + EPS);
    #pragma unroll
    for (int i = 0; i < DIM / 256; i++) {
        int d = tid + i * 256;
        out[(size_t)row * DIM + d] = vals[i] * rstd * w[d];
    }
}

// ---------------- host: tensormap encode ----------------
typedef CUresult (*PFN_tmEncode)(CUtensorMap*, CUtensorMapDataType, cuuint32_t, void*,
                                 const cuuint64_t*, const cuuint64_t*, const cuuint32_t*,
                                 const cuuint32_t*, CUtensorMapInterleave, CUtensorMapSwizzle,
                                 CUtensorMapL2promotion, CUtensorMapFloatOOBfill);

static PFN_tmEncode get_encoder() {
    void* p = nullptr;
#if CUDART_VERSION >= 12050
    cudaDriverEntryPointQueryResult qr;
    cudaGetDriverEntryPointByVersion("cuTensorMapEncodeTiled", &p, 12000,
                                     cudaEnableDefault, &qr);
#else
    cudaGetDriverEntryPoint("cuTensorMapEncodeTiled", &p, cudaEnableDefault);
#endif
    return (PFN_tmEncode)p;
}

static void enc2d(PFN_tmEncode enc, CUtensorMap* m, void* base,
                  uint64_t rows, uint32_t boxRows) {
    cuuint64_t dims[2]    = {GK, rows};
    cuuint64_t strides[1] = {GK * 2};
    cuuint32_t box[2]     = {32, boxRows};
    cuuint32_t es[2]      = {1, 1};
    enc(m, CU_TENSOR_MAP_DATA_TYPE_BFLOAT16, 2, base, dims, strides, box, es,
        CU_TENSOR_MAP_INTERLEAVE_NONE, CU_TENSOR_MAP_SWIZZLE_64B,
        CU_TENSOR_MAP_L2_PROMOTION_L2_128B, CU_TENSOR_MAP_FLOAT_OOB_FILL_NONE);
}

// ---------------- launch ----------------
extern "C" void kernel_launch(void* const* d_in, const int* in_sizes, int n_in,
                              void* d_out, int out_size) {
    const float* x      = (const float*)d_in[0];
    const float* attn_w = (const float*)d_in[1];
    const float* wq     = (const float*)d_in[2];
    const float* wkv    = (const float*)d_in[3];
    const float* wo     = (const float*)d_in[4];
    const float* out_w  = (const float*)d_in[5];
    float* out = (float*)d_out;

    float *pq, *pkv, *ptmp;
    __nv_bfloat16 *pah, *pal, *pbkvh, *pbkvl, *pbqh, *pbql, *pboh, *pbol;
    __nv_bfloat16 *pqnh, *pqnl, *poh, *pol;
    cudaGetSymbolAddress((void**)&pq,    g_q);
    cudaGetSymbolAddress((void**)&pkv,   g_kv);
    cudaGetSymbolAddress((void**)&ptmp,  g_tmp);
    cudaGetSymbolAddress((void**)&pah,   g_a_hi);
    cudaGetSymbolAddress((void**)&pal,   g_a_lo);
    cudaGetSymbolAddress((void**)&pbkvh, g_bkv_hi);
    cudaGetSymbolAddress((void**)&pbkvl, g_bkv_lo);
    cudaGetSymbolAddress((void**)&pbqh,  g_bq_hi);
    cudaGetSymbolAddress((void**)&pbql,  g_bq_lo);
    cudaGetSymbolAddress((void**)&pboh,  g_bo_hi);
    cudaGetSymbolAddress((void**)&pbol,  g_bo_lo);
    cudaGetSymbolAddress((void**)&pqnh,  g_qn_hi);
    cudaGetSymbolAddress((void**)&pqnl,  g_qn_lo);
    cudaGetSymbolAddress((void**)&poh,   g_o_hi);
    cudaGetSymbolAddress((void**)&pol,   g_o_lo);

    PFN_tmEncode enc = get_encoder();
    CUtensorMap mQA_h, mQA_l, mQB_h, mQB_l;
    CUtensorMap mKA_h, mKA_l, mKB_h, mKB_l;
    CUtensorMap mOA_h, mOA_l, mOB_h, mOB_l;
    enc2d(enc, &mQA_h, pqnh,  NQ,   128);  enc2d(enc, &mQA_l, pqnl,  NQ,   128);
    enc2d(enc, &mQB_h, pbqh,  DIM,  256);  enc2d(enc, &mQB_l, pbql,  DIM,  256);
    enc2d(enc, &mKA_h, pah,   NTOK, 128);  enc2d(enc, &mKA_l, pal,   NTOK, 128);
    enc2d(enc, &mKB_h, pbkvh, KVW,  256);  enc2d(enc, &mKB_l, pbkvl, KVW,  256);
    enc2d(enc, &mOA_h, poh,   NQ,   128);  enc2d(enc, &mOA_l, pol,   NQ,   128);
    enc2d(enc, &mOB_h, pboh,  DIM,  256);  enc2d(enc, &mOB_l, pbol,  DIM,  256);

    cudaFuncSetAttribute(attention2_kernel,
                         cudaFuncAttributeMaxDynamicSharedMemorySize, (int)ATT2_SMEM);
    cudaFuncSetAttribute(gemm3_kernel,
                         cudaFuncAttributeMaxDynamicSharedMemorySize, (int)GEMM_SMEM);

    // weight prep
    tsplit_kernel<<<dim3(KVW/32, DIM/32), dim3(32,8)>>>(wkv, pbkvh, pbkvl, DIM, KVW);
    tsplit_kernel<<<dim3(DIM/32, DIM/32), dim3(32,8)>>>(wq, pbqh, pbql, DIM, DIM);
    tsplit_kernel<<<dim3(DIM/32, DIM/32), dim3(32,8)>>>(wo, pboh, pbol, DIM, DIM);

    // fused x-split + pooling + attention rmsnorm
    pool_rmsnorm_kernel<<<NQ, 256>>>(x, attn_w);

    // q = qn @ wq
    gemm3_kernel<<<(NQ/BM)*(DIM/BN), 256, GEMM_SMEM>>>(DIM, NQ/BM, DIM/BN,
        mQA_h, mQA_l, mQB_h, mQB_l, pqnh, pqnl, pbqh, pbql, pq);
    // kv = x @ wkv
    gemm3_kernel<<<(NTOK/BM)*(KVW/BN), 256, GEMM_SMEM>>>(KVW, NTOK/BM, KVW/BN,
        mKA_h, mKA_l, mKB_h, mKB_l, pah, pal, pbkvh, pbkvl, pkv);
    // tensor-core attention
    attention2_kernel<<<SEGN * NH, 256, ATT2_SMEM>>>();
    // tmp = o @ wo
    gemm3_kernel<<<(NQ/BM)*(DIM/BN), 256, GEMM_SMEM>>>(DIM, NQ/BM, DIM/BN,
        mOA_h, mOA_l, mOB_h, mOB_l, poh, pol, pboh, pbol, ptmp);
    // residual + rmsnorm
    final_kernel<<<NQ, 256>>>(out_w, out);
}

// round 7
// speedup vs baseline: 13.0606x; 1.2040x over previous
#include <cuda_runtime.h>
#include <cuda.h>
#include <cuda_bf16.h>
#include <cuda_fp16.h>
#include <math.h>
#include <stdint.h>

// ---------------- problem constants ----------------
#define SEGN   32
#define LSEG   512
#define RQ     64
#define POOLN  8
#define NH     32
#define HDIM   128
#define DIM    4096
#define NQ     (SEGN*RQ)     // 2048
#define NTOK   (SEGN*LSEG)   // 16384
#define KVW    (2*NH*HDIM)   // 8192
#define EPS    1e-5f

#if defined(__CUDA_ARCH_FEAT_SM103_ALL) || defined(__CUDA_ARCH_FEAT_SM100_ALL)
#define TC_OK 1
#else
#define TC_OK 0
#endif

// ---------------- scratch ----------------
__device__ __align__(128) float g_queries[(size_t)NQ*DIM];
__device__ __align__(128) float g_q[(size_t)NQ*DIM];
__device__ __align__(128) float g_kv[(size_t)NTOK*KVW];
__device__ __align__(128) float g_tmp[(size_t)NQ*DIM];

__device__ __align__(128) __half g_a_hi[(size_t)NTOK*DIM];
__device__ __align__(128) __half g_a_lo[(size_t)NTOK*DIM];
__device__ __align__(128) __half g_bkv[(size_t)KVW*DIM];
__device__ __align__(128) __half g_bq[(size_t)DIM*DIM];
__device__ __align__(128) __half g_bo[(size_t)DIM*DIM];
__device__ __align__(128) __half g_qn_hi[(size_t)NQ*DIM];
__device__ __align__(128) __half g_qn_lo[(size_t)NQ*DIM];
__device__ __align__(128) __half g_o_hi[(size_t)NQ*DIM];
__device__ __align__(128) __half g_o_lo[(size_t)NQ*DIM];

// ---------------- generic helpers ----------------
__device__ __forceinline__ uint32_t s2u(const void* p) {
    return (uint32_t)__cvta_generic_to_shared(p);
}
__device__ __forceinline__ void mbar_init(uint32_t a, uint32_t cnt) {
    asm volatile("mbarrier.init.shared.b64 [%0], %1;" :: "r"(a), "r"(cnt) : "memory");
}
__device__ __forceinline__ void mbar_wait(uint32_t a, uint32_t phase) {
    uint32_t done;
    do {
        asm volatile("{\n\t.reg .pred p;\n\t"
                     "mbarrier.try_wait.parity.shared::cta.b64 p, [%1], %2, 0x989680;\n\t"
                     "selp.b32 %0, 1, 0, p;\n\t}"
                     : "=r"(done) : "r"(a), "r"(phase) : "memory");
    } while (!done);
}
__device__ __forceinline__ void mbar_expect_tx(uint32_t a, uint32_t bytes) {
    asm volatile("mbarrier.arrive.expect_tx.shared.b64 _, [%0], %1;"
                 :: "r"(a), "r"(bytes) : "memory");
}
__device__ __forceinline__ void tma_load_2d(uint32_t dst, const void* map,
                                            int cx, int cy, uint32_t bar) {
    asm volatile("cp.async.bulk.tensor.2d.shared::cta.global.tile.mbarrier::complete_tx::bytes "
                 "[%0], [%1, {%2, %3}], [%4];"
                 :: "r"(dst), "l"(map), "r"(cx), "r"(cy), "r"(bar) : "memory");
}
// bf16 mma (portable) — used by attention
__device__ __forceinline__ void mma16816(float* c, const uint32_t* a, uint32_t b0, uint32_t b1) {
    asm volatile("mma.sync.aligned.m16n8k16.row.col.f32.bf16.bf16.f32 "
                 "{%0,%1,%2,%3}, {%4,%5,%6,%7}, {%8,%9}, {%0,%1,%2,%3};"
                 : "+f"(c[0]), "+f"(c[1]), "+f"(c[2]), "+f"(c[3])
                 : "r"(a[0]), "r"(a[1]), "r"(a[2]), "r"(a[3]), "r"(b0), "r"(b1));
}
// fp16 mma (portable) — fallback GEMM
__device__ __forceinline__ void mma16816h(float* c, const uint32_t* a, uint32_t b0, uint32_t b1) {
    asm volatile("mma.sync.aligned.m16n8k16.row.col.f32.f16.f16.f32 "
                 "{%0,%1,%2,%3}, {%4,%5,%6,%7}, {%8,%9}, {%0,%1,%2,%3};"
                 : "+f"(c[0]), "+f"(c[1]), "+f"(c[2]), "+f"(c[3])
                 : "r"(a[0]), "r"(a[1]), "r"(a[2]), "r"(a[3]), "r"(b0), "r"(b1));
}
// split float2 -> packed bf16x2 hi + lo (attention internal)
__device__ __forceinline__ void split2(float2 v, uint32_t& hi, uint32_t& lo) {
    __nv_bfloat16 hx = __float2bfloat16(v.x), hy = __float2bfloat16(v.y);
    __nv_bfloat162 hp = __halves2bfloat162(hx, hy);
    hi = *(uint32_t*)&hp;
    __nv_bfloat162 lp = __halves2bfloat162(
        __float2bfloat16(v.x - __bfloat162float(hx)),
        __float2bfloat16(v.y - __bfloat162float(hy)));
    lo = *(uint32_t*)&lp;
}
// split float2 -> packed fp16x2 hi + lo
__device__ __forceinline__ void split2h(float2 v, uint32_t& hi, uint32_t& lo) {
    __half hx = __float2half_rn(v.x), hy = __float2half_rn(v.y);
    __half2 hp = __halves2half2(hx, hy);
    hi = *(uint32_t*)&hp;
    __half2 lp = __halves2half2(
        __float2half_rn(v.x - __half2float(hx)),
        __float2half_rn(v.y - __half2float(hy)));
    lo = *(uint32_t*)&lp;
}

#if TC_OK
// ---------------- tcgen05 helpers ('a' targets only) ----------------
__device__ __forceinline__ void tc_alloc(uint32_t smem_dst, uint32_t ncols) {
    asm volatile("tcgen05.alloc.cta_group::1.sync.aligned.shared::cta.b32 [%0], %1;"
                 :: "r"(smem_dst), "r"(ncols) : "memory");
}
__device__ __forceinline__ void tc_dealloc(uint32_t tmem, uint32_t ncols) {
    asm volatile("tcgen05.relinquish_alloc_permit.cta_group::1.sync.aligned;");
    asm volatile("tcgen05.dealloc.cta_group::1.sync.aligned.b32 %0, %1;" :: "r"(tmem), "r"(ncols));
}
__device__ __forceinline__ void tc_commit(uint32_t bar) {
    asm volatile("tcgen05.commit.cta_group::1.mbarrier::arrive::one.shared::cluster.b64 [%0];"
                 :: "r"(bar) : "memory");
}
__device__ __forceinline__ void tc_mma_f16_ss(uint32_t d, uint64_t ad, uint64_t bd,
                                              uint32_t idesc, uint32_t accum) {
    asm volatile("{\n\t.reg .pred p;\n\t"
                 "setp.ne.u32 p, %4, 0;\n\t"
                 "tcgen05.mma.cta_group::1.kind::f16 [%0], %1, %2, %3, {%5, %5, %5, %5}, p;\n\t}"
                 :: "r"(d), "l"(ad), "l"(bd), "r"(idesc), "r"(accum), "r"(0u) : "memory");
}
__device__ __forceinline__ void tc_fence_after() {
    asm volatile("tcgen05.fence::after_thread_sync;" ::: "memory");
}
#define LDTM_X32(r, addr) \
    asm volatile("tcgen05.ld.sync.aligned.32x32b.x32.b32 " \
        "{%0, %1, %2, %3, %4, %5, %6, %7, %8, %9, %10, %11, %12, %13, %14, %15, " \
        "%16, %17, %18, %19, %20, %21, %22, %23, %24, %25, %26, %27, %28, %29, %30, %31}, [%32];" \
        : "=r"((r)[0]), "=r"((r)[1]), "=r"((r)[2]), "=r"((r)[3]), \
          "=r"((r)[4]), "=r"((r)[5]), "=r"((r)[6]), "=r"((r)[7]), \
          "=r"((r)[8]), "=r"((r)[9]), "=r"((r)[10]), "=r"((r)[11]), \
          "=r"((r)[12]), "=r"((r)[13]), "=r"((r)[14]), "=r"((r)[15]), \
          "=r"((r)[16]), "=r"((r)[17]), "=r"((r)[18]), "=r"((r)[19]), \
          "=r"((r)[20]), "=r"((r)[21]), "=r"((r)[22]), "=r"((r)[23]), \
          "=r"((r)[24]), "=r"((r)[25]), "=r"((r)[26]), "=r"((r)[27]), \
          "=r"((r)[28]), "=r"((r)[29]), "=r"((r)[30]), "=r"((r)[31]) \
        : "r"(addr))
__device__ __forceinline__ void tc_wait_ld() {
    asm volatile("tcgen05.wait::ld.sync.aligned;" ::: "memory");
}
// SW64 K-major descriptor: layout=4, version=1, SBO=32 (8 rows x 64B), LBO=1
static __device__ __forceinline__ uint64_t make_desc64(uint32_t addr) {
    const uint64_t base = (uint64_t(4) << 61) | (uint64_t(1) << 46) |
                          (uint64_t(32) << 32) | (uint64_t(1) << 16);
    return base | ((uint64_t)(addr >> 4) & 0x3FFFull);
}
#endif

// ---------------- weight transpose -> fp16 (single) ----------------
// in: [Kdim, Ndim] fp32 row-major -> out: [Ndim, Kdim] fp16 (transposed)
__global__ void wsplit_kernel(const float* __restrict__ in,
                              __half* __restrict__ out,
                              int Kdim, int Ndim) {
    __shared__ float t[32][33];
    int n0 = blockIdx.x * 32, k0 = blockIdx.y * 32;
    int tx = threadIdx.x, ty = threadIdx.y;
    for (int r = ty; r < 32; r += 8)
        t[r][tx] = in[(size_t)(k0 + r) * Ndim + n0 + tx];
    __syncthreads();
    for (int r = ty; r < 32; r += 8)
        out[(size_t)(n0 + r) * Kdim + k0 + tx] = __float2half_rn(t[tx][r]);
}

// ---------------- fused: x split (fp16 hi/lo) + pooling + attention rmsnorm ----------------
__global__ void pool_rmsnorm_kernel(const float* __restrict__ x,
                                    const float* __restrict__ w) {
    int row = blockIdx.x;
    int tid = threadIdx.x;
    const float* base = x + (size_t)row * POOLN * DIM;
    float local = 0.f;
    for (int d = tid; d < DIM; d += 256) {
        float s = 0.f;
        #pragma unroll
        for (int p = 0; p < POOLN; p++) {
            float v = base[(size_t)p*DIM + d];
            __half h = __float2half_rn(v);
            size_t o = (size_t)(row * POOLN + p) * DIM + d;
            g_a_hi[o] = h;
            g_a_lo[o] = __float2half_rn(v - __half2float(h));
            s += v;
        }
        s *= (1.0f / POOLN);
        g_queries[(size_t)row*DIM + d] = s;
        local += s * s;
    }
    __shared__ float red[256];
    red[tid] = local; __syncthreads();
    for (int st = 128; st > 0; st >>= 1) {
        if (tid < st) red[tid] += red[tid + st];
        __syncthreads();
    }
    float rstd = rsqrtf(red[0] / DIM + EPS);
    for (int d = tid; d < DIM; d += 256) {
        float v = g_queries[(size_t)row*DIM + d] * rstd * w[d];
        __half h = __float2half_rn(v);
        g_qn_hi[(size_t)row*DIM + d] = h;
        g_qn_lo[(size_t)row*DIM + d] = __float2half_rn(v - __half2float(h));
    }
}

// ---------------- fp16x2 GEMM: C[M,N] = (Ah+Al)[M,K] @ B[N,K]^T ----------------
// 256x256 tiles, K-chunk 32, SW64 smem, 4 stages, TMA producer, 8 MMAs/chunk.
#define BM 256
#define BN 256
#define GK 4096
#define KITERS (GK/32)
#define A_TILE_B 8192u               // 128 rows x 64B
#define B_TILE_B 16384u              // 256 rows x 64B
#define STAGE_BYTES (4u*A_TILE_B + B_TILE_B)   // 49152
#define NSTAGE 4
#define GEMM_SMEM (NSTAGE*STAGE_BYTES + 1024)

__global__ __launch_bounds__(256, 1)
void gemm3_kernel(int N, int nbm, int nbn,
                  const __grid_constant__ CUtensorMap mAh,
                  const __grid_constant__ CUtensorMap mAl,
                  const __grid_constant__ CUtensorMap mB,
                  const __half* __restrict__ Ah,
                  const __half* __restrict__ Al,
                  const __half* __restrict__ B,
                  float* __restrict__ C) {
    extern __shared__ char smraw[];
    char* smp = (char*)((((uintptr_t)smraw) + 1023) & ~(uintptr_t)1023);
    int tid = threadIdx.x;

    const int GM = 16;
    int bid = blockIdx.x;
    int group = bid / (GM * nbn);
    int first_m = group * GM;
    int gsz = min(nbm - first_m, GM);
    int pm = first_m + (bid % gsz);
    int pn = (bid % (GM * nbn)) / gsz;
    int m0 = pm * BM, n0 = pn * BN;

#if TC_OK
    uint32_t sb0 = s2u(smp);
    __shared__ __align__(8) unsigned long long full_b[NSTAGE], empty_b[NSTAGE], fin_b;
    __shared__ uint32_t tmem_ptr_sh;

    uint32_t full_a[NSTAGE], empty_a[NSTAGE], fin_a;
    #pragma unroll
    for (int i = 0; i < NSTAGE; i++) {
        full_a[i] = s2u(&full_b[i]);
        empty_a[i] = s2u(&empty_b[i]);
    }
    fin_a = s2u(&fin_b);

    if (tid < 32) tc_alloc(s2u(&tmem_ptr_sh), 512);
    if (tid == 0) {
        #pragma unroll
        for (int i = 0; i < NSTAGE; i++) {
            mbar_init(full_a[i], 1);
            mbar_init(empty_a[i], 1);
        }
        mbar_init(fin_a, 1);
    }
    __syncthreads();
    uint32_t tmem = tmem_ptr_sh;

    // kind::f16, f16 inputs (atype=btype=0), f32 accum, M=128, N=256
    const uint32_t idesc = (1u<<4) | ((BN/8)<<17) | (8u<<24);

    if (tid == 32) {
        // TMA producer
        for (int it = 0; it < KITERS; it++) {
            int s = it % NSTAGE;
            uint32_t ph = ((it / NSTAGE) & 1) ^ 1u;
            mbar_wait(empty_a[s], ph);
            int k0 = it * 32;
            uint32_t sb = sb0 + s * STAGE_BYTES;
            uint32_t bar = full_a[s];
            mbar_expect_tx(bar, STAGE_BYTES);
            tma_load_2d(sb,                &mAh, k0, m0,       bar);
            tma_load_2d(sb + A_TILE_B,     &mAl, k0, m0,       bar);
            tma_load_2d(sb + 2u*A_TILE_B,  &mAh, k0, m0 + 128, bar);
            tma_load_2d(sb + 3u*A_TILE_B,  &mAl, k0, m0 + 128, bar);
            tma_load_2d(sb + 4u*A_TILE_B,  &mB,  k0, n0,       bar);
        }
    } else if (tid == 0) {
        // MMA issuer
        for (int it = 0; it < KITERS; it++) {
            int s = it % NSTAGE;
            uint32_t ph = (it / NSTAGE) & 1;
            mbar_wait(full_a[s], ph);
            uint32_t sb = sb0 + s * STAGE_BYTES;
            uint64_t a0h = make_desc64(sb);
            uint64_t a0l = make_desc64(sb + A_TILE_B);
            uint64_t a1h = make_desc64(sb + 2u*A_TILE_B);
            uint64_t a1l = make_desc64(sb + 3u*A_TILE_B);
            uint64_t bd  = make_desc64(sb + 4u*A_TILE_B);
            #pragma unroll
            for (int ks = 0; ks < 2; ks++) {
                uint32_t acc = (it > 0 || ks > 0) ? 1u : 0u;
                uint64_t o = ks * 2;
                tc_mma_f16_ss(tmem,       a0h + o, bd + o, idesc, acc);
                tc_mma_f16_ss(tmem + 256, a1h + o, bd + o, idesc, acc);
                tc_mma_f16_ss(tmem,       a0l + o, bd + o, idesc, 1u);
                tc_mma_f16_ss(tmem + 256, a1l + o, bd + o, idesc, 1u);
            }
            tc_commit(empty_a[s]);
        }
        tc_commit(fin_a);
    }

    __syncthreads();
    mbar_wait(fin_a, 0);
    tc_fence_after();

    float* stg = (float*)smp;
    int w = tid >> 5, lane = tid & 31;
    #pragma unroll
    for (int half = 0; half < 2; half++) {
        if (w < 4) {
            for (int ch = 0; ch < 8; ch++) {
                uint32_t r[32];
                LDTM_X32(r, tmem + half * 256 + ch * 32);
                tc_wait_ld();
                #pragma unroll
                for (int j = 0; j < 32; j++)
                    stg[(size_t)(w * 32 + lane) * 260 + ch * 32 + j] = __uint_as_float(r[j]);
            }
        }
        __syncthreads();
        int c4 = (tid & 63) * 4;
        for (int rr = tid >> 6; rr < 128; rr += 4) {
            float4 v = *(float4*)&stg[(size_t)rr * 260 + c4];
            *(float4*)&C[(size_t)(m0 + half * 128 + rr) * N + n0 + c4] = v;
        }
        __syncthreads();
    }
    if (tid < 32) tc_dealloc(tmem, 512);
#else
    // mma.sync fp16x2 fallback (bare sm_103; not selected on GB300)
    __half* sAh = (__half*)smp;
    __half* sAl = sAh + 128 * 40;
    __half* sB  = sAl + 128 * 40;

    int lane = tid & 31, w = tid >> 5;
    int wm = w & 3, wn = w >> 2;

    for (int mh = 0; mh < 2; mh++)
    for (int nh = 0; nh < 2; nh++) {
        int m0h = m0 + mh * 128;
        int n0h = n0 + nh * 128;
        float acc[2][4][4];
        #pragma unroll
        for (int mi = 0; mi < 2; mi++)
            #pragma unroll
            for (int ni = 0; ni < 4; ni++)
                #pragma unroll
                for (int j = 0; j < 4; j++) acc[mi][ni][j] = 0.f;

        for (int k0 = 0; k0 < GK; k0 += 32) {
            __syncthreads();
            for (int cid = tid; cid < 512; cid += 256) {
                int r = cid >> 2, c = cid & 3;
                *(uint4*)&sAh[r*40 + c*8] = *(const uint4*)&Ah[(size_t)(m0h+r)*GK + k0 + c*8];
                *(uint4*)&sAl[r*40 + c*8] = *(const uint4*)&Al[(size_t)(m0h+r)*GK + k0 + c*8];
                *(uint4*)&sB [r*40 + c*8] = *(const uint4*)&B [(size_t)(n0h+r)*GK + k0 + c*8];
            }
            __syncthreads();
            #pragma unroll
            for (int ks = 0; ks < 2; ks++) {
                int kc = (lane & 3) * 2 + ks * 16;
                uint32_t ah[2][4], al[2][4];
                #pragma unroll
                for (int mi = 0; mi < 2; mi++) {
                    int r = wm * 32 + mi * 16 + (lane >> 2);
                    ah[mi][0] = *(uint32_t*)&sAh[r*40 + kc];
                    ah[mi][1] = *(uint32_t*)&sAh[(r+8)*40 + kc];
                    ah[mi][2] = *(uint32_t*)&sAh[r*40 + kc + 8];
                    ah[mi][3] = *(uint32_t*)&sAh[(r+8)*40 + kc + 8];
                    al[mi][0] = *(uint32_t*)&sAl[r*40 + kc];
                    al[mi][1] = *(uint32_t*)&sAl[(r+8)*40 + kc];
                    al[mi][2] = *(uint32_t*)&sAl[r*40 + kc + 8];
                    al[mi][3] = *(uint32_t*)&sAl[(r+8)*40 + kc + 8];
                }
                #pragma unroll
                for (int ni = 0; ni < 4; ni++) {
                    int nr = wn * 64 + ni * 8 + (lane >> 2);
                    uint32_t b0 = *(uint32_t*)&sB[nr*40 + kc];
                    uint32_t b1 = *(uint32_t*)&sB[nr*40 + kc + 8];
                    #pragma unroll
                    for (int mi = 0; mi < 2; mi++) {
                        mma16816h(acc[mi][ni], ah[mi], b0, b1);
                        mma16816h(acc[mi][ni], al[mi], b0, b1);
                    }
                }
            }
        }
        #pragma unroll
        for (int mi = 0; mi < 2; mi++)
            #pragma unroll
            for (int ni = 0; ni < 4; ni++) {
                int r = m0h + wm * 32 + mi * 16 + (lane >> 2);
                int c = n0h + wn * 64 + ni * 8 + (lane & 3) * 2;
                *(float2*)&C[(size_t)r * N + c] = make_float2(acc[mi][ni][0], acc[mi][ni][1]);
                *(float2*)&C[(size_t)(r+8) * N + c] = make_float2(acc[mi][ni][2], acc[mi][ni][3]);
            }
    }
#endif
}

// ---------------- tensor-core attention (bf16x3 internal, fp16 hi/lo output) ----------------
#define SROW 514
#define QROW 132
#define VTROW 66
#define OFF_QH 131584
#define OFF_QL (OFF_QH + 16896)
#define OFF_KH (OFF_QL + 16896)
#define OFF_KL (OFF_KH + 16896)
#define OFF_RI (OFF_KL + 16896)
#define ATT2_SMEM (OFF_RI + 256)

__global__ __launch_bounds__(256, 1)
void attention2_kernel() {
    extern __shared__ char asmem[];
    float* sS = (float*)asmem;
    __nv_bfloat16* sQh = (__nv_bfloat16*)(asmem + OFF_QH);
    __nv_bfloat16* sQl = (__nv_bfloat16*)(asmem + OFF_QL);
    __nv_bfloat16* sKh = (__nv_bfloat16*)(asmem + OFF_KH);
    __nv_bfloat16* sKl = (__nv_bfloat16*)(asmem + OFF_KL);
    float* rinv = (float*)(asmem + OFF_RI);

    int tid = threadIdx.x;
    int h = blockIdx.x & 31;
    int s = blockIdx.x >> 5;
    int q0 = s * RQ;
    int t0 = s * LSEG;

    int w = tid >> 5, lane = tid & 31;
    int wm = w & 3, wn = w >> 2;
    int lr = lane >> 2, lc = lane & 3;

    for (int i = tid; i < 64 * 64; i += 256) {
        int r = i >> 6, c2 = (i & 63) * 2;
        float2 v = *(float2*)&g_q[(size_t)(q0 + r) * DIM + h * HDIM + c2];
        uint32_t hi, lo; split2(v, hi, lo);
        *(uint32_t*)&sQh[r * QROW + c2] = hi;
        *(uint32_t*)&sQl[r * QROW + c2] = lo;
    }

    const float scale = rsqrtf((float)HDIM);

    // ---- phase 1: S = scale * Q K^T ----
    for (int ck = 0; ck < 8; ck++) {
        __syncthreads();
        for (int i = tid; i < 64 * 64; i += 256) {
            int r = i >> 6, c2 = (i & 63) * 2;
            float2 v = *(float2*)&g_kv[(size_t)(t0 + ck * 64 + r) * KVW + h * HDIM + c2];
            uint32_t hi, lo; split2(v, hi, lo);
            *(uint32_t*)&sKh[r * QROW + c2] = hi;
            *(uint32_t*)&sKl[r * QROW + c2] = lo;
        }
        __syncthreads();

        float acc[4][4];
        #pragma unroll
        for (int nt = 0; nt < 4; nt++)
            #pragma unroll
            for (int j = 0; j < 4; j++) acc[nt][j] = 0.f;

        #pragma unroll
        for (int kk = 0; kk < 8; kk++) {
            int k0 = kk * 16;
            int r0 = wm * 16 + lr;
            uint32_t ah[4], al[4];
            ah[0] = *(uint32_t*)&sQh[r0 * QROW + k0 + lc * 2];
            ah[1] = *(uint32_t*)&sQh[(r0 + 8) * QROW + k0 + lc * 2];
            ah[2] = *(uint32_t*)&sQh[r0 * QROW + k0 + 8 + lc * 2];
            ah[3] = *(uint32_t*)&sQh[(r0 + 8) * QROW + k0 + 8 + lc * 2];
            al[0] = *(uint32_t*)&sQl[r0 * QROW + k0 + lc * 2];
            al[1] = *(uint32_t*)&sQl[(r0 + 8) * QROW + k0 + lc * 2];
            al[2] = *(uint32_t*)&sQl[r0 * QROW + k0 + 8 + lc * 2];
            al[3] = *(uint32_t*)&sQl[(r0 + 8) * QROW + k0 + 8 + lc * 2];
            #pragma unroll
            for (int nt = 0; nt < 4; nt++) {
                int nb = (wn * 4 + nt) * 8;
                uint32_t bh0 = *(uint32_t*)&sKh[(nb + lr) * QROW + k0 + lc * 2];
                uint32_t bh1 = *(uint32_t*)&sKh[(nb + lr) * QROW + k0 + 8 + lc * 2];
                uint32_t bl0 = *(uint32_t*)&sKl[(nb + lr) * QROW + k0 + lc * 2];
                uint32_t bl1 = *(uint32_t*)&sKl[(nb + lr) * QROW + k0 + 8 + lc * 2];
                mma16816(acc[nt], ah, bh0, bh1);
                mma16816(acc[nt], ah, bl0, bl1);
                mma16816(acc[nt], al, bh0, bh1);
            }
        }
        int row = wm * 16 + lr;
        #pragma unroll
        for (int nt = 0; nt < 4; nt++) {
            int col = ck * 64 + (wn * 4 + nt) * 8 + lc * 2;
            *(float2*)&sS[row * SROW + col] =
                make_float2(acc[nt][0] * scale, acc[nt][1] * scale);
            *(float2*)&sS[(row + 8) * SROW + col] =
                make_float2(acc[nt][2] * scale, acc[nt][3] * scale);
        }
    }
    __syncthreads();

    // ---- phase 2: softmax ----
    for (int j = 0; j < 8; j++) {
        int r = w * 8 + j;
        float m = -1e30f;
        for (int i = lane; i < LSEG; i += 32) m = fmaxf(m, sS[r * SROW + i]);
        #pragma unroll
        for (int o = 16; o; o >>= 1) m = fmaxf(m, __shfl_xor_sync(0xffffffffu, m, o));
        float sum = 0.f;
        for (int i = lane; i < LSEG; i += 32) {
            float e = __expf(sS[r * SROW + i] - m);
            sS[r * SROW + i] = e;
            sum += e;
        }
        #pragma unroll
        for (int o = 16; o; o >>= 1) sum += __shfl_xor_sync(0xffffffffu, sum, o);
        if (lane == 0) rinv[r] = 1.0f / sum;
    }

    // ---- phase 3: O = P V ----
    float oacc[8][4];
    #pragma unroll
    for (int nt = 0; nt < 8; nt++)
        #pragma unroll
        for (int j = 0; j < 4; j++) oacc[nt][j] = 0.f;

    for (int ck = 0; ck < 8; ck++) {
        __syncthreads();
        for (int i = tid; i < 64 * 64; i += 256) {
            int t = i >> 6, hd2 = (i & 63) * 2;
            float2 v = *(float2*)&g_kv[(size_t)(t0 + ck * 64 + t) * KVW
                                       + NH * HDIM + h * HDIM + hd2];
            __nv_bfloat16 hx = __float2bfloat16(v.x), hy = __float2bfloat16(v.y);
            sKh[hd2 * VTROW + t] = hx;
            sKh[(hd2 + 1) * VTROW + t] = hy;
            sKl[hd2 * VTROW + t] = __float2bfloat16(v.x - __bfloat162float(hx));
            sKl[(hd2 + 1) * VTROW + t] = __float2bfloat16(v.y - __bfloat162float(hy));
        }
        __syncthreads();

        #pragma unroll
        for (int kk = 0; kk < 4; kk++) {
            int kt = ck * 64 + kk * 16;
            int kl = kk * 16;
            int r0 = wm * 16 + lr;
            float2 p0 = *(float2*)&sS[r0 * SROW + kt + lc * 2];
            float2 p1 = *(float2*)&sS[(r0 + 8) * SROW + kt + lc * 2];
            float2 p2 = *(float2*)&sS[r0 * SROW + kt + 8 + lc * 2];
            float2 p3 = *(float2*)&sS[(r0 + 8) * SROW + kt + 8 + lc * 2];
            uint32_t ah[4], al[4];
            split2(p0, ah[0], al[0]);
            split2(p1, ah[1], al[1]);
            split2(p2, ah[2], al[2]);
            split2(p3, ah[3], al[3]);
            #pragma unroll
            for (int nt = 0; nt < 8; nt++) {
                int hd0 = wn * 64 + nt * 8;
                uint32_t bh0 = *(uint32_t*)&sKh[(hd0 + lr) * VTROW + kl + lc * 2];
                uint32_t bh1 = *(uint32_t*)&sKh[(hd0 + lr) * VTROW + kl + 8 + lc * 2];
                uint32_t bl0 = *(uint32_t*)&sKl[(hd0 + lr) * VTROW + kl + lc * 2];
                uint32_t bl1 = *(uint32_t*)&sKl[(hd0 + lr) * VTROW + kl + 8 + lc * 2];
                mma16816(oacc[nt], ah, bh0, bh1);
                mma16816(oacc[nt], al, bh0, bh1);
                mma16816(oacc[nt], ah, bl0, bl1);
            }
        }
    }

    // ---- writeback: normalize, emit fp16 hi/lo for o-projection ----
    {
        int r0 = wm * 16 + lr;
        float ri0 = rinv[r0], ri1 = rinv[r0 + 8];
        #pragma unroll
        for (int nt = 0; nt < 8; nt++) {
            int c0 = h * HDIM + wn * 64 + nt * 8 + lc * 2;
            uint32_t hi, lo;
            split2h(make_float2(oacc[nt][0] * ri0, oacc[nt][1] * ri0), hi, lo);
            *(uint32_t*)&g_o_hi[(size_t)(q0 + r0) * DIM + c0] = hi;
            *(uint32_t*)&g_o_lo[(size_t)(q0 + r0) * DIM + c0] = lo;
            split2h(make_float2(oacc[nt][2] * ri1, oacc[nt][3] * ri1), hi, lo);
            *(uint32_t*)&g_o_hi[(size_t)(q0 + r0 + 8) * DIM + c0] = hi;
            *(uint32_t*)&g_o_lo[(size_t)(q0 + r0 + 8) * DIM + c0] = lo;
        }
    }
}

// ---------------- final: residual + rmsnorm ----------------
__global__ void final_kernel(const float* __restrict__ w, float* __restrict__ out) {
    int row = blockIdx.x;
    int tid = threadIdx.x;
    float vals[DIM / 256];
    float local = 0.f;
    #pragma unroll
    for (int i = 0; i < DIM / 256; i++) {
        int d = tid + i * 256;
        float v = g_tmp[(size_t)row * DIM + d] + g_queries[(size_t)row * DIM + d];
        vals[i] = v;
        local += v * v;
    }
    __shared__ float red[256];
    red[tid] = local; __syncthreads();
    for (int st = 128; st > 0; st >>= 1) {
        if (tid < st) red[tid] += red[tid + st];
        __syncthreads();
    }
    float rstd = rsqrtf(red[0] / DIM + EPS);
    #pragma unroll
    for (int i = 0; i < DIM / 256; i++) {
        int d = tid + i * 256;
        out[(size_t)row * DIM + d] = vals[i] * rstd * w[d];
    }
}

// ---------------- host: tensormap encode ----------------
typedef CUresult (*PFN_tmEncode)(CUtensorMap*, CUtensorMapDataType, cuuint32_t, void*,
                                 const cuuint64_t*, const cuuint64_t*, const cuuint32_t*,
                                 const cuuint32_t*, CUtensorMapInterleave, CUtensorMapSwizzle,
                                 CUtensorMapL2promotion, CUtensorMapFloatOOBfill);

static PFN_tmEncode get_encoder() {
    void* p = nullptr;
#if CUDART_VERSION >= 12050
    cudaDriverEntryPointQueryResult qr;
    cudaGetDriverEntryPointByVersion("cuTensorMapEncodeTiled", &p, 12000,
                                     cudaEnableDefault, &qr);
#else
    cudaGetDriverEntryPoint("cuTensorMapEncodeTiled", &p, cudaEnableDefault);
#endif
    return (PFN_tmEncode)p;
}

static void enc2d(PFN_tmEncode enc, CUtensorMap* m, void* base,
                  uint64_t rows, uint32_t boxRows) {
    cuuint64_t dims[2]    = {GK, rows};
    cuuint64_t strides[1] = {GK * 2};
    cuuint32_t box[2]     = {32, boxRows};
    cuuint32_t es[2]      = {1, 1};
    enc(m, CU_TENSOR_MAP_DATA_TYPE_FLOAT16, 2, base, dims, strides, box, es,
        CU_TENSOR_MAP_INTERLEAVE_NONE, CU_TENSOR_MAP_SWIZZLE_64B,
        CU_TENSOR_MAP_L2_PROMOTION_L2_128B, CU_TENSOR_MAP_FLOAT_OOB_FILL_NONE);
}

// ---------------- launch ----------------
extern "C" void kernel_launch(void* const* d_in, const int* in_sizes, int n_in,
                              void* d_out, int out_size) {
    const float* x      = (const float*)d_in[0];
    const float* attn_w = (const float*)d_in[1];
    const float* wq     = (const float*)d_in[2];
    const float* wkv    = (const float*)d_in[3];
    const float* wo     = (const float*)d_in[4];
    const float* out_w  = (const float*)d_in[5];
    float* out = (float*)d_out;

    float *pq, *pkv, *ptmp;
    __half *pah, *pal, *pbkv, *pbq, *pbo, *pqnh, *pqnl, *poh, *pol;
    cudaGetSymbolAddress((void**)&pq,   g_q);
    cudaGetSymbolAddress((void**)&pkv,  g_kv);
    cudaGetSymbolAddress((void**)&ptmp, g_tmp);
    cudaGetSymbolAddress((void**)&pah,  g_a_hi);
    cudaGetSymbolAddress((void**)&pal,  g_a_lo);
    cudaGetSymbolAddress((void**)&pbkv, g_bkv);
    cudaGetSymbolAddress((void**)&pbq,  g_bq);
    cudaGetSymbolAddress((void**)&pbo,  g_bo);
    cudaGetSymbolAddress((void**)&pqnh, g_qn_hi);
    cudaGetSymbolAddress((void**)&pqnl, g_qn_lo);
    cudaGetSymbolAddress((void**)&poh,  g_o_hi);
    cudaGetSymbolAddress((void**)&pol,  g_o_lo);

    PFN_tmEncode enc = get_encoder();
    CUtensorMap mQA_h, mQA_l, mQB;
    CUtensorMap mKA_h, mKA_l, mKB;
    CUtensorMap mOA_h, mOA_l, mOB;
    enc2d(enc, &mQA_h, pqnh, NQ,   128);
    enc2d(enc, &mQA_l, pqnl, NQ,   128);
    enc2d(enc, &mQB,   pbq,  DIM,  256);
    enc2d(enc, &mKA_h, pah,  NTOK, 128);
    enc2d(enc, &mKA_l, pal,  NTOK, 128);
    enc2d(enc, &mKB,   pbkv, KVW,  256);
    enc2d(enc, &mOA_h, poh,  NQ,   128);
    enc2d(enc, &mOA_l, pol,  NQ,   128);
    enc2d(enc, &mOB,   pbo,  DIM,  256);

    cudaFuncSetAttribute(attention2_kernel,
                         cudaFuncAttributeMaxDynamicSharedMemorySize, (int)ATT2_SMEM);
    cudaFuncSetAttribute(gemm3_kernel,
                         cudaFuncAttributeMaxDynamicSharedMemorySize, (int)GEMM_SMEM);

    // weight prep (transpose -> fp16)
    wsplit_kernel<<<dim3(KVW/32, DIM/32), dim3(32,8)>>>(wkv, pbkv, DIM, KVW);
    wsplit_kernel<<<dim3(DIM/32, DIM/32), dim3(32,8)>>>(wq, pbq, DIM, DIM);
    wsplit_kernel<<<dim3(DIM/32, DIM/32), dim3(32,8)>>>(wo, pbo, DIM, DIM);

    // fused x-split + pooling + attention rmsnorm
    pool_rmsnorm_kernel<<<NQ, 256>>>(x, attn_w);

    // q = qn @ wq
    gemm3_kernel<<<(NQ/BM)*(DIM/BN), 256, GEMM_SMEM>>>(DIM, NQ/BM, DIM/BN,
        mQA_h, mQA_l, mQB, pqnh, pqnl, pbq, pq);
    // kv = x @ wkv
    gemm3_kernel<<<(NTOK/BM)*(KVW/BN), 256, GEMM_SMEM>>>(KVW, NTOK/BM, KVW/BN,
        mKA_h, mKA_l, mKB, pah, pal, pbkv, pkv);
    // tensor-core attention
    attention2_kernel<<<SEGN * NH, 256, ATT2_SMEM>>>();
    // tmp = o @ wo
    gemm3_kernel<<<(NQ/BM)*(DIM/BN), 256, GEMM_SMEM>>>(DIM, NQ/BM, DIM/BN,
        mOA_h, mOA_l, mOB, poh, pol, pbo, ptmp);
    // residual + rmsnorm
    final_kernel<<<NQ, 256>>>(out_w, out);
}